// round 1
// baseline (speedup 1.0000x reference)
#include <cuda_runtime.h>
#include <cuda_bf16.h>
#include <cstddef>

// Problem constants (fixed by reference)
#define BATCH 4
#define SEQ   2048
#define DMODEL 1024
#define NHEADS 16
#define HD     64
#define TOKENS (BATCH * SEQ)          // 8192
#define D3     (3 * DMODEL)           // 3072

// Scratch (static device allocations — allowed)
__device__ float g_proj[(size_t)TOKENS * D3];    // 96 MB: [token, 3072] = Q|K|V
__device__ float g_ctx [(size_t)TOKENS * DMODEL]; // 32 MB: [token, 1024]

// ---------------------------------------------------------------------------
// SGEMM: C[M,N] = A[M,K] @ B[K,N] + bias[N]
// 128x128 block tile, BK=8, 256 threads, 8x8 per-thread microtile.
// All dims divisible by tile sizes for this problem (M=8192, N in {3072,1024}, K=1024).
// ---------------------------------------------------------------------------
#define BM 128
#define BN 128
#define BK 8
#define TM 8
#define TN 8

__global__ __launch_bounds__(256) void sgemm_bias_kernel(
    const float* __restrict__ A, const float* __restrict__ B,
    const float* __restrict__ bias, float* __restrict__ C,
    int M, int N, int K)
{
    __shared__ float As[BK][BM];
    __shared__ float Bs[BK][BN];

    const int tid = threadIdx.x;
    const int m0 = blockIdx.y * BM;
    const int n0 = blockIdx.x * BN;

    const int ty = tid >> 4;          // 0..15
    const int tx = tid & 15;          // 0..15
    const int rowBase = ty * TM;      // 0..120
    const int colBase = tx * TN;      // 0..120

    // A tile load mapping: thread -> (row, 4-col chunk)
    const int ar = tid >> 1;              // 0..127
    const int ac = (tid & 1) << 2;        // 0 or 4
    // B tile load mapping
    const int br = tid >> 5;              // 0..7
    const int bc = (tid & 31) << 2;       // 0..124

    float acc[TM][TN];
    #pragma unroll
    for (int i = 0; i < TM; i++)
        #pragma unroll
        for (int j = 0; j < TN; j++)
            acc[i][j] = 0.f;

    for (int k0 = 0; k0 < K; k0 += BK) {
        float4 av = *(const float4*)(A + (size_t)(m0 + ar) * K + k0 + ac);
        As[ac + 0][ar] = av.x;
        As[ac + 1][ar] = av.y;
        As[ac + 2][ar] = av.z;
        As[ac + 3][ar] = av.w;
        *(float4*)&Bs[br][bc] = *(const float4*)(B + (size_t)(k0 + br) * N + n0 + bc);
        __syncthreads();

        #pragma unroll
        for (int k = 0; k < BK; k++) {
            float a[TM], b[TN];
            #pragma unroll
            for (int i = 0; i < TM; i += 4)
                *(float4*)&a[i] = *(const float4*)&As[k][rowBase + i];
            #pragma unroll
            for (int j = 0; j < TN; j += 4)
                *(float4*)&b[j] = *(const float4*)&Bs[k][colBase + j];
            #pragma unroll
            for (int i = 0; i < TM; i++)
                #pragma unroll
                for (int j = 0; j < TN; j++)
                    acc[i][j] = fmaf(a[i], b[j], acc[i][j]);
        }
        __syncthreads();
    }

    #pragma unroll
    for (int i = 0; i < TM; i++) {
        const int row = m0 + rowBase + i;
        #pragma unroll
        for (int j = 0; j < TN; j += 4) {
            const int col = n0 + colBase + j;
            float4 o;
            o.x = acc[i][j + 0] + bias[col + 0];
            o.y = acc[i][j + 1] + bias[col + 1];
            o.z = acc[i][j + 2] + bias[col + 2];
            o.w = acc[i][j + 3] + bias[col + 3];
            *(float4*)&C[(size_t)row * N + col] = o;
        }
    }
}

// ---------------------------------------------------------------------------
// Flash attention: one thread per query row, 64-key smem tiles, online softmax
// with lazy rescale (rescale-o only when running max changes).
// proj layout: [token, 3072] with Q at col 0, K at 1024, V at 2048; head h
// occupies 64-col slice h*64 within each third.
// Output: ctx[token, 1024], head slice h*64.
// ---------------------------------------------------------------------------
#define QROWS 128
#define KTILE 64

__global__ __launch_bounds__(128) void flash_attn_kernel(
    const float* __restrict__ proj, float* __restrict__ ctx)
{
    __shared__ float Kt[KTILE][HD];
    __shared__ float Vt[KTILE][HD];

    const int b = blockIdx.y >> 4;
    const int h = blockIdx.y & 15;
    const int row = blockIdx.x * QROWS + threadIdx.x;
    const int token = b * SEQ + row;

    // load q, pre-scale by 1/sqrt(hd) = 0.125
    float q[HD];
    {
        const float* qptr = proj + (size_t)token * D3 + h * HD;
        #pragma unroll
        for (int c = 0; c < HD; c += 4) {
            float4 v = *(const float4*)(qptr + c);
            q[c + 0] = v.x * 0.125f;
            q[c + 1] = v.y * 0.125f;
            q[c + 2] = v.z * 0.125f;
            q[c + 3] = v.w * 0.125f;
        }
    }

    float m = -1e30f, l = 0.f;
    float o[HD];
    #pragma unroll
    for (int c = 0; c < HD; c++) o[c] = 0.f;

    const size_t kbase = (size_t)b * SEQ * D3 + DMODEL + h * HD; // K slice
    const size_t vbase = kbase + DMODEL;                          // V slice

    for (int kv0 = 0; kv0 < SEQ; kv0 += KTILE) {
        // cooperative tile load: 64x64 floats for K and V (8 float4 each/thread)
        #pragma unroll
        for (int i = 0; i < 8; i++) {
            const int f = threadIdx.x + i * 128;   // 0..1023
            const int kr = f >> 4;
            const int c4 = (f & 15) << 2;
            const size_t roff = (size_t)(kv0 + kr) * D3 + c4;
            *(float4*)&Kt[kr][c4] = *(const float4*)(proj + kbase + roff);
            *(float4*)&Vt[kr][c4] = *(const float4*)(proj + vbase + roff);
        }
        __syncthreads();

        for (int kk = 0; kk < KTILE; kk++) {
            float s = 0.f;
            #pragma unroll
            for (int c = 0; c < HD; c++)
                s = fmaf(q[c], Kt[kk][c], s);

            if (s <= m) {
                const float p = __expf(s - m);
                l += p;
                #pragma unroll
                for (int c = 0; c < HD; c++)
                    o[c] = fmaf(p, Vt[kk][c], o[c]);
            } else {
                const float alpha = __expf(m - s);   // exp(-huge)=0 on first key: safe
                m = s;
                l = fmaf(l, alpha, 1.f);
                #pragma unroll
                for (int c = 0; c < HD; c++)
                    o[c] = fmaf(o[c], alpha, Vt[kk][c]);
            }
        }
        __syncthreads();
    }

    const float inv = 1.f / l;
    float* optr = ctx + (size_t)token * DMODEL + h * HD;
    #pragma unroll
    for (int c = 0; c < HD; c += 4) {
        float4 v;
        v.x = o[c + 0] * inv;
        v.y = o[c + 1] * inv;
        v.z = o[c + 2] * inv;
        v.w = o[c + 3] * inv;
        *(float4*)(optr + c) = v;
    }
}

// ---------------------------------------------------------------------------
// Launch
// ---------------------------------------------------------------------------
extern "C" void kernel_launch(void* const* d_in, const int* in_sizes, int n_in,
                              void* d_out, int out_size)
{
    const float* qkv   = (const float*)d_in[0];  // [4,2048,1024]
    const float* W_in  = (const float*)d_in[1];  // [1024,3072]
    const float* b_in  = (const float*)d_in[2];  // [3072]
    const float* W_out = (const float*)d_in[3];  // [1024,1024]
    const float* b_out = (const float*)d_in[4];  // [1024]
    float* out = (float*)d_out;                  // [4,2048,1024]

    static float* p_proj = nullptr;
    static float* p_ctx  = nullptr;
    if (!p_proj) {
        cudaGetSymbolAddress((void**)&p_proj, g_proj);
        cudaGetSymbolAddress((void**)&p_ctx,  g_ctx);
    }

    // 1) proj = qkv @ W_in + b_in
    {
        dim3 grid(D3 / BN, TOKENS / BM);   // 24 x 64
        sgemm_bias_kernel<<<grid, 256>>>(qkv, W_in, b_in, p_proj, TOKENS, D3, DMODEL);
    }

    // 2) attention -> ctx
    {
        dim3 grid(SEQ / QROWS, BATCH * NHEADS);  // 16 x 64
        flash_attn_kernel<<<grid, 128>>>(p_proj, p_ctx);
    }

    // 3) out = ctx @ W_out + b_out
    {
        dim3 grid(DMODEL / BN, TOKENS / BM);  // 8 x 64
        sgemm_bias_kernel<<<grid, 256>>>(p_ctx, W_out, b_out, out, TOKENS, DMODEL, DMODEL);
    }
}

// round 2
// speedup vs baseline: 1.2993x; 1.2993x over previous
#include <cuda_runtime.h>
#include <cuda_bf16.h>
#include <cstdint>
#include <cstddef>

// Problem constants
#define BATCH 4
#define SEQ   2048
#define DMODEL 1024
#define NHEADS 16
#define HD     64
#define TOKENS (BATCH * SEQ)          // 8192
#define D3     (3 * DMODEL)           // 3072

// Scratch
__device__ float g_proj[(size_t)TOKENS * D3];     // 96 MB
__device__ float g_ctx [(size_t)TOKENS * DMODEL]; // 32 MB

// ---------------------------------------------------------------------------
// TF32 tensor-core GEMM: C[M,N] = A[M,K] @ B[K,N] + bias[N]
// 128x128x32 block tile, 256 threads (8 warps, each 64x32), mma.m16n8k8 tf32.
// A in smem: [128][32] fp32-as-tf32, SW128 swizzle, fetched via ldmatrix.x4.
// B in smem: [32][136] (8-word pad -> conflict-free scalar frag loads).
// Register-staged double buffering.
// ---------------------------------------------------------------------------
#define BSTRIDE 136                      // 128 + 8 pad words
#define A_BUF_WORDS (128 * 32)           // 4096
#define B_BUF_WORDS (32 * BSTRIDE)       // 4352
#define SMEM_WORDS  (2 * A_BUF_WORDS + 2 * B_BUF_WORDS)
#define SMEM_BYTES  (SMEM_WORDS * 4)     // 67584

__device__ __forceinline__ uint32_t f2tf32(float f) {
    uint32_t r;
    asm("cvt.rna.tf32.f32 %0, %1;" : "=r"(r) : "f"(f));
    return r;
}

__device__ __forceinline__ void mma_tf32(
    float& c0, float& c1, float& c2, float& c3,
    uint32_t a0, uint32_t a1, uint32_t a2, uint32_t a3,
    uint32_t b0, uint32_t b1)
{
    asm volatile(
        "mma.sync.aligned.m16n8k8.row.col.f32.tf32.tf32.f32 "
        "{%0,%1,%2,%3}, {%4,%5,%6,%7}, {%8,%9}, {%0,%1,%2,%3};\n"
        : "+f"(c0), "+f"(c1), "+f"(c2), "+f"(c3)
        : "r"(a0), "r"(a1), "r"(a2), "r"(a3), "r"(b0), "r"(b1));
}

__global__ __launch_bounds__(256) void tf32_gemm_bias(
    const float* __restrict__ A, const float* __restrict__ B,
    const float* __restrict__ bias, float* __restrict__ C,
    int M, int N, int K)
{
    extern __shared__ uint32_t smem[];
    uint32_t* As = smem;                         // 2 buffers of [128][32]
    uint32_t* Bs = smem + 2 * A_BUF_WORDS;       // 2 buffers of [32][136]
    const uint32_t smem_u32 = (uint32_t)__cvta_generic_to_shared(smem);

    const int tid  = threadIdx.x;
    const int lane = tid & 31;
    const int w    = tid >> 5;
    const int wm   = (w & 1) * 64;   // warp M offset in tile
    const int wn   = (w >> 1) * 32;  // warp N offset in tile
    const int m0   = blockIdx.y * 128;
    const int n0   = blockIdx.x * 128;

    // staging mapping
    const int a_row = tid >> 3;      // 0..31 (stride 32 over 128 rows)
    const int a_k4  = tid & 7;       // float4 index within 32-wide K
    const int b_k   = tid >> 5;      // 0..7 (stride 8 over 32 rows)
    const int b_n4  = tid & 31;      // float4 index within 128-wide N

    float acc[4][4][4];
    #pragma unroll
    for (int mt = 0; mt < 4; mt++)
        #pragma unroll
        for (int nt = 0; nt < 4; nt++)
            #pragma unroll
            for (int r = 0; r < 4; r++)
                acc[mt][nt][r] = 0.f;

    const int ITERS = K >> 5;

    // ---- prologue: stage tile 0 into buffer 0 ----
    {
        #pragma unroll
        for (int i = 0; i < 4; i++) {
            const int row = a_row + i * 32;
            float4 v = *(const float4*)(A + (size_t)(m0 + row) * K + a_k4 * 4);
            uint4 t = { f2tf32(v.x), f2tf32(v.y), f2tf32(v.z), f2tf32(v.w) };
            const int wrd = (row * 128 + ((a_k4 ^ (row & 7)) << 4)) >> 2;
            *(uint4*)(As + wrd) = t;
        }
        #pragma unroll
        for (int i = 0; i < 4; i++) {
            const int k = b_k + i * 8;
            float4 v = *(const float4*)(B + (size_t)k * N + n0 + b_n4 * 4);
            uint4 t = { f2tf32(v.x), f2tf32(v.y), f2tf32(v.z), f2tf32(v.w) };
            *(uint4*)(Bs + k * BSTRIDE + b_n4 * 4) = t;
        }
    }
    __syncthreads();

    int buf = 0;
    float4 a_reg[4], b_reg[4];

    for (int it = 0; it < ITERS; ++it) {
        const bool has_next = (it + 1 < ITERS);
        if (has_next) {
            const int k0 = (it + 1) << 5;
            #pragma unroll
            for (int i = 0; i < 4; i++)
                a_reg[i] = *(const float4*)(A + (size_t)(m0 + a_row + i * 32) * K + k0 + a_k4 * 4);
            #pragma unroll
            for (int i = 0; i < 4; i++)
                b_reg[i] = *(const float4*)(B + (size_t)(k0 + b_k + i * 8) * N + n0 + b_n4 * 4);
        }

        // ---- compute from buffer `buf` ----
        const uint32_t aBase = smem_u32 + buf * (A_BUF_WORDS * 4);
        const uint32_t* BsBuf = Bs + buf * B_BUF_WORDS;

        #pragma unroll
        for (int ks = 0; ks < 4; ks++) {
            uint32_t af[4][4];
            #pragma unroll
            for (int mt = 0; mt < 4; mt++) {
                const int row = wm + mt * 16 + (lane & 15);
                const int c = (ks << 1) + (lane >> 4);
                const uint32_t addr = aBase + row * 128 + ((c ^ (row & 7)) << 4);
                asm volatile(
                    "ldmatrix.sync.aligned.m8n8.x4.shared.b16 {%0,%1,%2,%3}, [%4];"
                    : "=r"(af[mt][0]), "=r"(af[mt][1]), "=r"(af[mt][2]), "=r"(af[mt][3])
                    : "r"(addr));
            }
            uint32_t bf[4][2];
            #pragma unroll
            for (int nt = 0; nt < 4; nt++) {
                const int wrd = ((ks << 3) + (lane & 3)) * BSTRIDE + wn + nt * 8 + (lane >> 2);
                bf[nt][0] = BsBuf[wrd];
                bf[nt][1] = BsBuf[wrd + 4 * BSTRIDE];
            }
            #pragma unroll
            for (int mt = 0; mt < 4; mt++)
                #pragma unroll
                for (int nt = 0; nt < 4; nt++)
                    mma_tf32(acc[mt][nt][0], acc[mt][nt][1], acc[mt][nt][2], acc[mt][nt][3],
                             af[mt][0], af[mt][1], af[mt][2], af[mt][3],
                             bf[nt][0], bf[nt][1]);
        }

        if (has_next) {
            uint32_t* Ad = As + (buf ^ 1) * A_BUF_WORDS;
            uint32_t* Bd = Bs + (buf ^ 1) * B_BUF_WORDS;
            #pragma unroll
            for (int i = 0; i < 4; i++) {
                const int row = a_row + i * 32;
                float4 v = a_reg[i];
                uint4 t = { f2tf32(v.x), f2tf32(v.y), f2tf32(v.z), f2tf32(v.w) };
                const int wrd = (row * 128 + ((a_k4 ^ (row & 7)) << 4)) >> 2;
                *(uint4*)(Ad + wrd) = t;
            }
            #pragma unroll
            for (int i = 0; i < 4; i++) {
                const int k = b_k + i * 8;
                float4 v = b_reg[i];
                uint4 t = { f2tf32(v.x), f2tf32(v.y), f2tf32(v.z), f2tf32(v.w) };
                *(uint4*)(Bd + k * BSTRIDE + b_n4 * 4) = t;
            }
            __syncthreads();
            buf ^= 1;
        }
    }

    // ---- epilogue: bias + store ----
    #pragma unroll
    for (int mt = 0; mt < 4; mt++) {
        const int r0 = m0 + wm + mt * 16 + (lane >> 2);
        const int r1 = r0 + 8;
        #pragma unroll
        for (int nt = 0; nt < 4; nt++) {
            const int col = n0 + wn + nt * 8 + ((lane & 3) << 1);
            const float bx = bias[col], by = bias[col + 1];
            float2 v0 = { acc[mt][nt][0] + bx, acc[mt][nt][1] + by };
            float2 v1 = { acc[mt][nt][2] + bx, acc[mt][nt][3] + by };
            *(float2*)(C + (size_t)r0 * N + col) = v0;
            *(float2*)(C + (size_t)r1 * N + col) = v1;
        }
    }
}

// ---------------------------------------------------------------------------
// Flash attention (unchanged SIMT version): one thread per query row.
// ---------------------------------------------------------------------------
#define QROWS 128
#define KTILE 64

__global__ __launch_bounds__(128) void flash_attn_kernel(
    const float* __restrict__ proj, float* __restrict__ ctx)
{
    __shared__ float Kt[KTILE][HD];
    __shared__ float Vt[KTILE][HD];

    const int b = blockIdx.y >> 4;
    const int h = blockIdx.y & 15;
    const int row = blockIdx.x * QROWS + threadIdx.x;
    const int token = b * SEQ + row;

    float q[HD];
    {
        const float* qptr = proj + (size_t)token * D3 + h * HD;
        #pragma unroll
        for (int c = 0; c < HD; c += 4) {
            float4 v = *(const float4*)(qptr + c);
            q[c + 0] = v.x * 0.125f;
            q[c + 1] = v.y * 0.125f;
            q[c + 2] = v.z * 0.125f;
            q[c + 3] = v.w * 0.125f;
        }
    }

    float m = -1e30f, l = 0.f;
    float o[HD];
    #pragma unroll
    for (int c = 0; c < HD; c++) o[c] = 0.f;

    const size_t kbase = (size_t)b * SEQ * D3 + DMODEL + h * HD;
    const size_t vbase = kbase + DMODEL;

    for (int kv0 = 0; kv0 < SEQ; kv0 += KTILE) {
        #pragma unroll
        for (int i = 0; i < 8; i++) {
            const int f = threadIdx.x + i * 128;
            const int kr = f >> 4;
            const int c4 = (f & 15) << 2;
            const size_t roff = (size_t)(kv0 + kr) * D3 + c4;
            *(float4*)&Kt[kr][c4] = *(const float4*)(proj + kbase + roff);
            *(float4*)&Vt[kr][c4] = *(const float4*)(proj + vbase + roff);
        }
        __syncthreads();

        for (int kk = 0; kk < KTILE; kk++) {
            float s = 0.f;
            #pragma unroll
            for (int c = 0; c < HD; c++)
                s = fmaf(q[c], Kt[kk][c], s);

            if (s <= m) {
                const float p = __expf(s - m);
                l += p;
                #pragma unroll
                for (int c = 0; c < HD; c++)
                    o[c] = fmaf(p, Vt[kk][c], o[c]);
            } else {
                const float alpha = __expf(m - s);
                m = s;
                l = fmaf(l, alpha, 1.f);
                #pragma unroll
                for (int c = 0; c < HD; c++)
                    o[c] = fmaf(o[c], alpha, Vt[kk][c]);
            }
        }
        __syncthreads();
    }

    const float inv = 1.f / l;
    float* optr = ctx + (size_t)token * DMODEL + h * HD;
    #pragma unroll
    for (int c = 0; c < HD; c += 4) {
        float4 v;
        v.x = o[c + 0] * inv;
        v.y = o[c + 1] * inv;
        v.z = o[c + 2] * inv;
        v.w = o[c + 3] * inv;
        *(float4*)(optr + c) = v;
    }
}

// ---------------------------------------------------------------------------
// Launch
// ---------------------------------------------------------------------------
extern "C" void kernel_launch(void* const* d_in, const int* in_sizes, int n_in,
                              void* d_out, int out_size)
{
    const float* qkv   = (const float*)d_in[0];
    const float* W_in  = (const float*)d_in[1];
    const float* b_in  = (const float*)d_in[2];
    const float* W_out = (const float*)d_in[3];
    const float* b_out = (const float*)d_in[4];
    float* out = (float*)d_out;

    static float* p_proj = nullptr;
    static float* p_ctx  = nullptr;
    if (!p_proj) {
        cudaGetSymbolAddress((void**)&p_proj, g_proj);
        cudaGetSymbolAddress((void**)&p_ctx,  g_ctx);
        cudaFuncSetAttribute(tf32_gemm_bias,
                             cudaFuncAttributeMaxDynamicSharedMemorySize, SMEM_BYTES);
    }

    // 1) proj = qkv @ W_in + b_in   [8192 x 3072 x 1024]
    {
        dim3 grid(D3 / 128, TOKENS / 128);   // 24 x 64
        tf32_gemm_bias<<<grid, 256, SMEM_BYTES>>>(qkv, W_in, b_in, p_proj, TOKENS, D3, DMODEL);
    }

    // 2) attention -> ctx
    {
        dim3 grid(SEQ / QROWS, BATCH * NHEADS);  // 16 x 64
        flash_attn_kernel<<<grid, 128>>>(p_proj, p_ctx);
    }

    // 3) out = ctx @ W_out + b_out  [8192 x 1024 x 1024]
    {
        dim3 grid(DMODEL / 128, TOKENS / 128);   // 8 x 64
        tf32_gemm_bias<<<grid, 256, SMEM_BYTES>>>(p_ctx, W_out, b_out, out, TOKENS, DMODEL, DMODEL);
    }
}

// round 4
// speedup vs baseline: 3.7683x; 2.9004x over previous
#include <cuda_runtime.h>
#include <cuda_bf16.h>
#include <cstdint>
#include <cstddef>

// Problem constants
#define BATCH 4
#define SEQ   2048
#define DMODEL 1024
#define NHEADS 16
#define HD     64
#define TOKENS (BATCH * SEQ)          // 8192
#define D3     (3 * DMODEL)           // 3072

// Scratch
__device__ float g_proj[(size_t)TOKENS * D3];     // 96 MB
__device__ float g_ctx [(size_t)TOKENS * DMODEL]; // 32 MB

__device__ __forceinline__ uint32_t f2tf32(float f) {
    uint32_t r;
    asm("cvt.rna.tf32.f32 %0, %1;" : "=r"(r) : "f"(f));
    return r;
}

__device__ __forceinline__ void mma_tf32(
    float& c0, float& c1, float& c2, float& c3,
    uint32_t a0, uint32_t a1, uint32_t a2, uint32_t a3,
    uint32_t b0, uint32_t b1)
{
    asm volatile(
        "mma.sync.aligned.m16n8k8.row.col.f32.tf32.tf32.f32 "
        "{%0,%1,%2,%3}, {%4,%5,%6,%7}, {%8,%9}, {%0,%1,%2,%3};\n"
        : "+f"(c0), "+f"(c1), "+f"(c2), "+f"(c3)
        : "r"(a0), "r"(a1), "r"(a2), "r"(a3), "r"(b0), "r"(b1));
}

// ---------------------------------------------------------------------------
// TF32 tensor-core GEMM: C[M,N] = A[M,K] @ B[K,N] + bias[N]
// 128x128x32 block tile, 256 threads (8 warps, each 64x32), mma.m16n8k8 tf32.
// ---------------------------------------------------------------------------
#define BSTRIDE 136
#define A_BUF_WORDS (128 * 32)
#define B_BUF_WORDS (32 * BSTRIDE)
#define SMEM_WORDS  (2 * A_BUF_WORDS + 2 * B_BUF_WORDS)
#define SMEM_BYTES  (SMEM_WORDS * 4)

__global__ __launch_bounds__(256) void tf32_gemm_bias(
    const float* __restrict__ A, const float* __restrict__ B,
    const float* __restrict__ bias, float* __restrict__ C,
    int M, int N, int K)
{
    extern __shared__ uint32_t smem[];
    uint32_t* As = smem;
    uint32_t* Bs = smem + 2 * A_BUF_WORDS;
    const uint32_t smem_u32 = (uint32_t)__cvta_generic_to_shared(smem);

    const int tid  = threadIdx.x;
    const int lane = tid & 31;
    const int w    = tid >> 5;
    const int wm   = (w & 1) * 64;
    const int wn   = (w >> 1) * 32;
    const int m0   = blockIdx.y * 128;
    const int n0   = blockIdx.x * 128;

    const int a_row = tid >> 3;
    const int a_k4  = tid & 7;
    const int b_k   = tid >> 5;
    const int b_n4  = tid & 31;

    float acc[4][4][4];
    #pragma unroll
    for (int mt = 0; mt < 4; mt++)
        #pragma unroll
        for (int nt = 0; nt < 4; nt++)
            #pragma unroll
            for (int r = 0; r < 4; r++)
                acc[mt][nt][r] = 0.f;

    const int ITERS = K >> 5;

    {
        #pragma unroll
        for (int i = 0; i < 4; i++) {
            const int row = a_row + i * 32;
            float4 v = *(const float4*)(A + (size_t)(m0 + row) * K + a_k4 * 4);
            uint4 t = { f2tf32(v.x), f2tf32(v.y), f2tf32(v.z), f2tf32(v.w) };
            const int wrd = (row * 128 + ((a_k4 ^ (row & 7)) << 4)) >> 2;
            *(uint4*)(As + wrd) = t;
        }
        #pragma unroll
        for (int i = 0; i < 4; i++) {
            const int k = b_k + i * 8;
            float4 v = *(const float4*)(B + (size_t)k * N + n0 + b_n4 * 4);
            uint4 t = { f2tf32(v.x), f2tf32(v.y), f2tf32(v.z), f2tf32(v.w) };
            *(uint4*)(Bs + k * BSTRIDE + b_n4 * 4) = t;
        }
    }
    __syncthreads();

    int buf = 0;
    float4 a_reg[4], b_reg[4];

    for (int it = 0; it < ITERS; ++it) {
        const bool has_next = (it + 1 < ITERS);
        if (has_next) {
            const int k0 = (it + 1) << 5;
            #pragma unroll
            for (int i = 0; i < 4; i++)
                a_reg[i] = *(const float4*)(A + (size_t)(m0 + a_row + i * 32) * K + k0 + a_k4 * 4);
            #pragma unroll
            for (int i = 0; i < 4; i++)
                b_reg[i] = *(const float4*)(B + (size_t)(k0 + b_k + i * 8) * N + n0 + b_n4 * 4);
        }

        const uint32_t aBase = smem_u32 + buf * (A_BUF_WORDS * 4);
        const uint32_t* BsBuf = Bs + buf * B_BUF_WORDS;

        #pragma unroll
        for (int ks = 0; ks < 4; ks++) {
            uint32_t af[4][4];
            #pragma unroll
            for (int mt = 0; mt < 4; mt++) {
                const int row = wm + mt * 16 + (lane & 15);
                const int c = (ks << 1) + (lane >> 4);
                const uint32_t addr = aBase + row * 128 + ((c ^ (row & 7)) << 4);
                asm volatile(
                    "ldmatrix.sync.aligned.m8n8.x4.shared.b16 {%0,%1,%2,%3}, [%4];"
                    : "=r"(af[mt][0]), "=r"(af[mt][1]), "=r"(af[mt][2]), "=r"(af[mt][3])
                    : "r"(addr));
            }
            uint32_t bf[4][2];
            #pragma unroll
            for (int nt = 0; nt < 4; nt++) {
                const int wrd = ((ks << 3) + (lane & 3)) * BSTRIDE + wn + nt * 8 + (lane >> 2);
                bf[nt][0] = BsBuf[wrd];
                bf[nt][1] = BsBuf[wrd + 4 * BSTRIDE];
            }
            #pragma unroll
            for (int mt = 0; mt < 4; mt++)
                #pragma unroll
                for (int nt = 0; nt < 4; nt++)
                    mma_tf32(acc[mt][nt][0], acc[mt][nt][1], acc[mt][nt][2], acc[mt][nt][3],
                             af[mt][0], af[mt][1], af[mt][2], af[mt][3],
                             bf[nt][0], bf[nt][1]);
        }

        if (has_next) {
            uint32_t* Ad = As + (buf ^ 1) * A_BUF_WORDS;
            uint32_t* Bd = Bs + (buf ^ 1) * B_BUF_WORDS;
            #pragma unroll
            for (int i = 0; i < 4; i++) {
                const int row = a_row + i * 32;
                float4 v = a_reg[i];
                uint4 t = { f2tf32(v.x), f2tf32(v.y), f2tf32(v.z), f2tf32(v.w) };
                const int wrd = (row * 128 + ((a_k4 ^ (row & 7)) << 4)) >> 2;
                *(uint4*)(Ad + wrd) = t;
            }
            #pragma unroll
            for (int i = 0; i < 4; i++) {
                const int k = b_k + i * 8;
                float4 v = b_reg[i];
                uint4 t = { f2tf32(v.x), f2tf32(v.y), f2tf32(v.z), f2tf32(v.w) };
                *(uint4*)(Bd + k * BSTRIDE + b_n4 * 4) = t;
            }
            __syncthreads();
            buf ^= 1;
        }
    }

    #pragma unroll
    for (int mt = 0; mt < 4; mt++) {
        const int r0 = m0 + wm + mt * 16 + (lane >> 2);
        const int r1 = r0 + 8;
        #pragma unroll
        for (int nt = 0; nt < 4; nt++) {
            const int col = n0 + wn + nt * 8 + ((lane & 3) << 1);
            const float bx = bias[col], by = bias[col + 1];
            float2 v0 = { acc[mt][nt][0] + bx, acc[mt][nt][1] + by };
            float2 v1 = { acc[mt][nt][2] + bx, acc[mt][nt][3] + by };
            *(float2*)(C + (size_t)r0 * N + col) = v0;
            *(float2*)(C + (size_t)r1 * N + col) = v1;
        }
    }
}

// ---------------------------------------------------------------------------
// Tensor-core flash attention (tf32 mma).
// Block: 256 threads = 8 warps; 128 query rows per block, one (b,h).
// Per 64-key tile: S = Q K^T (HMMA) -> fragment online softmax -> P via smem
// -> O += P V (HMMA).
// smem strides: Qs/Ps 68 (ldmatrix phase conflict-free), Kt 68 (4n+j distinct),
// Vt 72 (8k+n distinct).
// ---------------------------------------------------------------------------
#define QS_OFF 0
#define PS_OFF 8704            // 128*68
#define KT_OFF 17408           // + 128*68
#define VT_OFF 21760           // + 64*68
#define FA_SMEM_WORDS 26368    // + 64*72
#define FA_SMEM_BYTES (FA_SMEM_WORDS * 4)

__global__ __launch_bounds__(256) void flash_attn_tc(
    const float* __restrict__ proj, float* __restrict__ ctx)
{
    extern __shared__ uint32_t sm[];
    uint32_t* Qs = sm + QS_OFF;
    uint32_t* Ps = sm + PS_OFF;
    uint32_t* Kt = sm + KT_OFF;
    uint32_t* Vt = sm + VT_OFF;
    const uint32_t smem_u32 = (uint32_t)__cvta_generic_to_shared(sm);
    const uint32_t QsB = smem_u32 + QS_OFF * 4;
    const uint32_t PsB = smem_u32 + PS_OFF * 4;

    const int tid  = threadIdx.x;
    const int lane = tid & 31;
    const int w    = tid >> 5;
    const int wm   = w * 16;
    const int b    = blockIdx.y >> 4;
    const int h    = blockIdx.y & 15;
    const int q0   = blockIdx.x * 128;

    // ---- stage Q (scaled by 1/8, tf32) ----
    {
        const float* qptr = proj + (size_t)(b * SEQ + q0) * D3 + h * HD;
        #pragma unroll
        for (int i = 0; i < 8; i++) {
            const int f = tid + i * 256;
            const int row = f >> 4;
            const int c4 = (f & 15) << 2;
            float4 v = *(const float4*)(qptr + (size_t)row * D3 + c4);
            uint4 t = { f2tf32(v.x * 0.125f), f2tf32(v.y * 0.125f),
                        f2tf32(v.z * 0.125f), f2tf32(v.w * 0.125f) };
            *(uint4*)(Qs + row * 68 + c4) = t;
        }
    }
    __syncthreads();

    // ---- preload Q fragments ----
    uint32_t qf[8][4];
    #pragma unroll
    for (int ks = 0; ks < 8; ks++) {
        const uint32_t addr = QsB + (wm + (lane & 15)) * 272 + ks * 32 + ((lane >> 4) << 4);
        asm volatile(
            "ldmatrix.sync.aligned.m8n8.x4.shared.b16 {%0,%1,%2,%3}, [%4];"
            : "=r"(qf[ks][0]), "=r"(qf[ks][1]), "=r"(qf[ks][2]), "=r"(qf[ks][3])
            : "r"(addr));
    }

    float o[8][4];
    #pragma unroll
    for (int nt = 0; nt < 8; nt++)
        #pragma unroll
        for (int r = 0; r < 4; r++)
            o[nt][r] = 0.f;
    float m0v = -1e30f, m1v = -1e30f, l0 = 0.f, l1 = 0.f;

    const float* kptr = proj + (size_t)b * SEQ * D3 + DMODEL + h * HD;
    const float* vptr = kptr + DMODEL;

    for (int kv0 = 0; kv0 < SEQ; kv0 += 64) {
        __syncthreads();   // previous tile's Kt/Vt reads complete
        // ---- stage K, V (tf32) ----
        #pragma unroll
        for (int i = 0; i < 4; i++) {
            const int f = tid + i * 256;
            const int row = f >> 4;
            const int c4 = (f & 15) << 2;
            const size_t g = (size_t)(kv0 + row) * D3 + c4;
            float4 kv = *(const float4*)(kptr + g);
            uint4 tk = { f2tf32(kv.x), f2tf32(kv.y), f2tf32(kv.z), f2tf32(kv.w) };
            *(uint4*)(Kt + row * 68 + c4) = tk;
            float4 vv = *(const float4*)(vptr + g);
            uint4 tv = { f2tf32(vv.x), f2tf32(vv.y), f2tf32(vv.z), f2tf32(vv.w) };
            *(uint4*)(Vt + row * 72 + c4) = tv;
        }
        __syncthreads();

        // ---- S = Q K^T ----
        float s[8][4];
        #pragma unroll
        for (int nt = 0; nt < 8; nt++)
            #pragma unroll
            for (int r = 0; r < 4; r++)
                s[nt][r] = 0.f;

        #pragma unroll
        for (int ks = 0; ks < 8; ks++) {
            #pragma unroll
            for (int nt = 0; nt < 8; nt++) {
                const int base = (nt * 8 + (lane >> 2)) * 68 + ks * 8 + (lane & 3);
                const uint32_t b0 = Kt[base];
                const uint32_t b1 = Kt[base + 4];
                mma_tf32(s[nt][0], s[nt][1], s[nt][2], s[nt][3],
                         qf[ks][0], qf[ks][1], qf[ks][2], qf[ks][3], b0, b1);
            }
        }

        // ---- online softmax on fragments ----
        float mx0 = -1e30f, mx1 = -1e30f;
        #pragma unroll
        for (int nt = 0; nt < 8; nt++) {
            mx0 = fmaxf(mx0, fmaxf(s[nt][0], s[nt][1]));
            mx1 = fmaxf(mx1, fmaxf(s[nt][2], s[nt][3]));
        }
        mx0 = fmaxf(mx0, __shfl_xor_sync(0xffffffffu, mx0, 1));
        mx0 = fmaxf(mx0, __shfl_xor_sync(0xffffffffu, mx0, 2));
        mx1 = fmaxf(mx1, __shfl_xor_sync(0xffffffffu, mx1, 1));
        mx1 = fmaxf(mx1, __shfl_xor_sync(0xffffffffu, mx1, 2));

        const float mn0 = fmaxf(m0v, mx0);
        const float mn1 = fmaxf(m1v, mx1);
        const float a0 = __expf(m0v - mn0);
        const float a1 = __expf(m1v - mn1);
        m0v = mn0; m1v = mn1;

        float sum0 = 0.f, sum1 = 0.f;
        #pragma unroll
        for (int nt = 0; nt < 8; nt++) {
            s[nt][0] = __expf(s[nt][0] - mn0);
            s[nt][1] = __expf(s[nt][1] - mn0);
            s[nt][2] = __expf(s[nt][2] - mn1);
            s[nt][3] = __expf(s[nt][3] - mn1);
            sum0 += s[nt][0] + s[nt][1];
            sum1 += s[nt][2] + s[nt][3];
        }
        sum0 += __shfl_xor_sync(0xffffffffu, sum0, 1);
        sum0 += __shfl_xor_sync(0xffffffffu, sum0, 2);
        sum1 += __shfl_xor_sync(0xffffffffu, sum1, 1);
        sum1 += __shfl_xor_sync(0xffffffffu, sum1, 2);
        l0 = l0 * a0 + sum0;
        l1 = l1 * a1 + sum1;

        #pragma unroll
        for (int nt = 0; nt < 8; nt++) {
            o[nt][0] *= a0; o[nt][1] *= a0;
            o[nt][2] *= a1; o[nt][3] *= a1;
        }

        // ---- store P to smem (tf32) ----
        {
            const int r = wm + (lane >> 2);
            #pragma unroll
            for (int nt = 0; nt < 8; nt++) {
                uint32_t* p0 = Ps + r * 68 + nt * 8 + ((lane & 3) << 1);
                uint2 t0 = { f2tf32(s[nt][0]), f2tf32(s[nt][1]) };
                *(uint2*)p0 = t0;
                uint2 t1 = { f2tf32(s[nt][2]), f2tf32(s[nt][3]) };
                *(uint2*)(p0 + 8 * 68) = t1;
            }
        }
        __syncwarp();

        // ---- O += P V ----
        #pragma unroll
        for (int ks = 0; ks < 8; ks++) {
            uint32_t pf[4];
            const uint32_t addr = PsB + (wm + (lane & 15)) * 272 + ks * 32 + ((lane >> 4) << 4);
            asm volatile(
                "ldmatrix.sync.aligned.m8n8.x4.shared.b16 {%0,%1,%2,%3}, [%4];"
                : "=r"(pf[0]), "=r"(pf[1]), "=r"(pf[2]), "=r"(pf[3])
                : "r"(addr));
            #pragma unroll
            for (int nt = 0; nt < 8; nt++) {
                const int base = (ks * 8 + (lane & 3)) * 72 + nt * 8 + (lane >> 2);
                const uint32_t b0 = Vt[base];
                const uint32_t b1 = Vt[base + 4 * 72];
                mma_tf32(o[nt][0], o[nt][1], o[nt][2], o[nt][3],
                         pf[0], pf[1], pf[2], pf[3], b0, b1);
            }
        }
    }

    // ---- epilogue ----
    const float inv0 = 1.f / l0;
    const float inv1 = 1.f / l1;
    const int tok0 = b * SEQ + q0 + wm + (lane >> 2);
    #pragma unroll
    for (int nt = 0; nt < 8; nt++) {
        const int col = h * HD + nt * 8 + ((lane & 3) << 1);
        float2 v0 = { o[nt][0] * inv0, o[nt][1] * inv0 };
        float2 v1 = { o[nt][2] * inv1, o[nt][3] * inv1 };
        *(float2*)(ctx + (size_t)tok0 * DMODEL + col) = v0;
        *(float2*)(ctx + (size_t)(tok0 + 8) * DMODEL + col) = v1;
    }
}

// ---------------------------------------------------------------------------
// Launch
// ---------------------------------------------------------------------------
extern "C" void kernel_launch(void* const* d_in, const int* in_sizes, int n_in,
                              void* d_out, int out_size)
{
    const float* qkv   = (const float*)d_in[0];
    const float* W_in  = (const float*)d_in[1];
    const float* b_in  = (const float*)d_in[2];
    const float* W_out = (const float*)d_in[3];
    const float* b_out = (const float*)d_in[4];
    float* out = (float*)d_out;

    static float* p_proj = nullptr;
    static float* p_ctx  = nullptr;
    if (!p_proj) {
        cudaGetSymbolAddress((void**)&p_proj, g_proj);
        cudaGetSymbolAddress((void**)&p_ctx,  g_ctx);
        cudaFuncSetAttribute(tf32_gemm_bias,
                             cudaFuncAttributeMaxDynamicSharedMemorySize, SMEM_BYTES);
        cudaFuncSetAttribute(flash_attn_tc,
                             cudaFuncAttributeMaxDynamicSharedMemorySize, FA_SMEM_BYTES);
    }

    // 1) proj = qkv @ W_in + b_in   [8192 x 3072 x 1024]
    {
        dim3 grid(D3 / 128, TOKENS / 128);
        tf32_gemm_bias<<<grid, 256, SMEM_BYTES>>>(qkv, W_in, b_in, p_proj, TOKENS, D3, DMODEL);
    }

    // 2) attention -> ctx (tensor core)
    {
        dim3 grid(SEQ / 128, BATCH * NHEADS);   // 16 x 64
        flash_attn_tc<<<grid, 256, FA_SMEM_BYTES>>>(p_proj, p_ctx);
    }

    // 3) out = ctx @ W_out + b_out  [8192 x 1024 x 1024]
    {
        dim3 grid(DMODEL / 128, TOKENS / 128);
        tf32_gemm_bias<<<grid, 256, SMEM_BYTES>>>(p_ctx, W_out, b_out, out, TOKENS, DMODEL, DMODEL);
    }
}

// round 5
// speedup vs baseline: 4.9459x; 1.3125x over previous
#include <cuda_runtime.h>
#include <cuda_bf16.h>
#include <cstdint>
#include <cstddef>

// Problem constants
#define BATCH 4
#define SEQ   2048
#define DMODEL 1024
#define NHEADS 16
#define HD     64
#define TOKENS (BATCH * SEQ)          // 8192
#define D3     (3 * DMODEL)           // 3072

// Scratch
__device__ float g_proj [(size_t)TOKENS * D3];     // 96 MB (tf32-rounded by GEMM1)
__device__ float g_ctx  [(size_t)TOKENS * DMODEL]; // 32 MB (tf32-rounded by attn)
__device__ float g_qkv_r[(size_t)TOKENS * DMODEL]; // 32 MB rounded qkv
__device__ float g_win_r[(size_t)DMODEL * D3];     // 12 MB rounded W_in
__device__ float g_wout_r[(size_t)DMODEL * DMODEL];//  4 MB rounded W_out

__device__ __forceinline__ uint32_t f2tf32(float f) {
    uint32_t r;
    asm("cvt.rna.tf32.f32 %0, %1;" : "=r"(r) : "f"(f));
    return r;
}
__device__ __forceinline__ float roundtf(float f) { return __uint_as_float(f2tf32(f)); }

__device__ __forceinline__ void mma_tf32(
    float& c0, float& c1, float& c2, float& c3,
    uint32_t a0, uint32_t a1, uint32_t a2, uint32_t a3,
    uint32_t b0, uint32_t b1)
{
    asm volatile(
        "mma.sync.aligned.m16n8k8.row.col.f32.tf32.tf32.f32 "
        "{%0,%1,%2,%3}, {%4,%5,%6,%7}, {%8,%9}, {%0,%1,%2,%3};\n"
        : "+f"(c0), "+f"(c1), "+f"(c2), "+f"(c3)
        : "r"(a0), "r"(a1), "r"(a2), "r"(a3), "r"(b0), "r"(b1));
}

__device__ __forceinline__ void cp_async16(uint32_t dst, const void* src) {
    asm volatile("cp.async.cg.shared.global [%0], [%1], 16;" :: "r"(dst), "l"(src));
}
#define CP_COMMIT() asm volatile("cp.async.commit_group;")
#define CP_WAIT(n)  asm volatile("cp.async.wait_group %0;" :: "n"(n))

// ---------------------------------------------------------------------------
// Prepass: round fp32 array to tf32 (rna), vectorized.
// ---------------------------------------------------------------------------
__global__ void round_tf32_kernel(const float4* __restrict__ in,
                                  float4* __restrict__ out, int n4)
{
    int i = blockIdx.x * blockDim.x + threadIdx.x;
    const int stride = gridDim.x * blockDim.x;
    for (; i < n4; i += stride) {
        float4 v = in[i];
        float4 r = { roundtf(v.x), roundtf(v.y), roundtf(v.z), roundtf(v.w) };
        out[i] = r;
    }
}

// ---------------------------------------------------------------------------
// TF32 GEMM with cp.async staging. Inputs already tf32-rounded.
// C = A @ B + bias; optional tf32 rounding of output.
// 128x128x32 tile, 256 threads, 8 warps (64x32 each), double-buffered cp.async.
// ---------------------------------------------------------------------------
#define BSTRIDE 136
#define A_BUF_WORDS (128 * 32)           // 4096
#define B_BUF_WORDS (32 * BSTRIDE)       // 4352
#define A_BUF_BYTES (A_BUF_WORDS * 4)
#define B_BUF_BYTES (B_BUF_WORDS * 4)
#define SMEM_BYTES  (2 * (A_BUF_BYTES + B_BUF_BYTES))   // 67584

__global__ __launch_bounds__(256, 2) void tf32_gemm_cp(
    const float* __restrict__ A, const float* __restrict__ B,
    const float* __restrict__ bias, float* __restrict__ C,
    int M, int N, int K, int round_out)
{
    extern __shared__ uint32_t smem[];
    uint32_t* Bs = smem + 2 * A_BUF_WORDS;
    const uint32_t smem_u32 = (uint32_t)__cvta_generic_to_shared(smem);
    const uint32_t bByteBase = smem_u32 + 2 * A_BUF_BYTES;

    const int tid  = threadIdx.x;
    const int lane = tid & 31;
    const int w    = tid >> 5;
    const int wm   = (w & 1) * 64;
    const int wn   = (w >> 1) * 32;
    const int m0   = blockIdx.y * 128;
    const int n0   = blockIdx.x * 128;

    const int a_row = tid >> 3;      // 0..31
    const int a_k4  = tid & 7;
    const int b_k   = tid >> 5;      // 0..7
    const int b_n4  = tid & 31;

    float acc[4][4][4];
    #pragma unroll
    for (int mt = 0; mt < 4; mt++)
        #pragma unroll
        for (int nt = 0; nt < 4; nt++)
            #pragma unroll
            for (int r = 0; r < 4; r++)
                acc[mt][nt][r] = 0.f;

    const int ITERS = K >> 5;

    auto stage = [&](int buf, int k0) {
        const uint32_t aDst = smem_u32 + buf * A_BUF_BYTES;
        #pragma unroll
        for (int i = 0; i < 4; i++) {
            const int row = a_row + i * 32;
            const int dstw = row * 32 + ((a_k4 ^ (row & 7)) << 2);
            cp_async16(aDst + dstw * 4, A + (size_t)(m0 + row) * K + k0 + a_k4 * 4);
        }
        const uint32_t bDst = bByteBase + buf * B_BUF_BYTES;
        #pragma unroll
        for (int i = 0; i < 4; i++) {
            const int k = b_k + i * 8;
            cp_async16(bDst + (k * BSTRIDE + b_n4 * 4) * 4,
                       B + (size_t)(k0 + k) * N + n0 + b_n4 * 4);
        }
    };

    stage(0, 0);
    CP_COMMIT();

    int buf = 0;
    for (int it = 0; it < ITERS; ++it) {
        const bool has_next = (it + 1 < ITERS);
        if (has_next) {
            stage(buf ^ 1, (it + 1) << 5);
            CP_COMMIT();
            CP_WAIT(1);
        } else {
            CP_WAIT(0);
        }
        __syncthreads();

        const uint32_t aBase = smem_u32 + buf * A_BUF_BYTES;
        const uint32_t* BsBuf = Bs + buf * B_BUF_WORDS;

        #pragma unroll
        for (int ks = 0; ks < 4; ks++) {
            uint32_t af[4][4];
            #pragma unroll
            for (int mt = 0; mt < 4; mt++) {
                const int row = wm + mt * 16 + (lane & 15);
                const int c = (ks << 1) + (lane >> 4);
                const uint32_t addr = aBase + row * 128 + ((c ^ (row & 7)) << 4);
                asm volatile(
                    "ldmatrix.sync.aligned.m8n8.x4.shared.b16 {%0,%1,%2,%3}, [%4];"
                    : "=r"(af[mt][0]), "=r"(af[mt][1]), "=r"(af[mt][2]), "=r"(af[mt][3])
                    : "r"(addr));
            }
            uint32_t bf[4][2];
            #pragma unroll
            for (int nt = 0; nt < 4; nt++) {
                const int wrd = ((ks << 3) + (lane & 3)) * BSTRIDE + wn + nt * 8 + (lane >> 2);
                bf[nt][0] = BsBuf[wrd];
                bf[nt][1] = BsBuf[wrd + 4 * BSTRIDE];
            }
            #pragma unroll
            for (int mt = 0; mt < 4; mt++)
                #pragma unroll
                for (int nt = 0; nt < 4; nt++)
                    mma_tf32(acc[mt][nt][0], acc[mt][nt][1], acc[mt][nt][2], acc[mt][nt][3],
                             af[mt][0], af[mt][1], af[mt][2], af[mt][3],
                             bf[nt][0], bf[nt][1]);
        }
        __syncthreads();
        buf ^= 1;
    }

    #pragma unroll
    for (int mt = 0; mt < 4; mt++) {
        const int r0 = m0 + wm + mt * 16 + (lane >> 2);
        const int r1 = r0 + 8;
        #pragma unroll
        for (int nt = 0; nt < 4; nt++) {
            const int col = n0 + wn + nt * 8 + ((lane & 3) << 1);
            const float bx = bias[col], by = bias[col + 1];
            float2 v0 = { acc[mt][nt][0] + bx, acc[mt][nt][1] + by };
            float2 v1 = { acc[mt][nt][2] + bx, acc[mt][nt][3] + by };
            if (round_out) {
                v0.x = roundtf(v0.x); v0.y = roundtf(v0.y);
                v1.x = roundtf(v1.x); v1.y = roundtf(v1.y);
            }
            *(float2*)(C + (size_t)r0 * N + col) = v0;
            *(float2*)(C + (size_t)r1 * N + col) = v1;
        }
    }
}

// ---------------------------------------------------------------------------
// Tensor-core flash attention, cp.async double-buffered K/V, ldmatrix K frags.
// proj is already tf32-rounded. ctx written tf32-rounded.
// ---------------------------------------------------------------------------
#define QS_OFF 0
#define PS_OFF 8704                     // 128*68
#define KT_OFF 17408
#define KT_BUF_WORDS (64 * 68)          // 4352
#define VT_OFF (KT_OFF + 2 * KT_BUF_WORDS)   // 26112
#define VT_BUF_WORDS (64 * 72)          // 4608
#define FA_SMEM_WORDS (VT_OFF + 2 * VT_BUF_WORDS)  // 35328
#define FA_SMEM_BYTES (FA_SMEM_WORDS * 4)          // 141312

__global__ __launch_bounds__(256) void flash_attn_tc(
    const float* __restrict__ proj, float* __restrict__ ctx)
{
    extern __shared__ uint32_t sm[];
    uint32_t* Qs = sm + QS_OFF;
    uint32_t* Ps = sm + PS_OFF;
    const uint32_t smem_u32 = (uint32_t)__cvta_generic_to_shared(sm);
    const uint32_t QsB = smem_u32 + QS_OFF * 4;
    const uint32_t PsB = smem_u32 + PS_OFF * 4;
    const uint32_t KtB = smem_u32 + KT_OFF * 4;
    const uint32_t VtB = smem_u32 + VT_OFF * 4;

    const int tid  = threadIdx.x;
    const int lane = tid & 31;
    const int w    = tid >> 5;
    const int wm   = w * 16;
    const int b    = blockIdx.y >> 4;
    const int h    = blockIdx.y & 15;
    const int q0   = blockIdx.x * 128;

    const float* kptr = proj + (size_t)b * SEQ * D3 + DMODEL + h * HD;
    const float* vptr = kptr + DMODEL;

    // staging maps
    const int st_row = tid >> 4;         // 0..15 (x4 -> 64 rows)
    const int st_c4  = (tid & 15) << 2;  // d offset

    auto stage_kv = [&](int buf, int kv0) {
        const uint32_t kDst = KtB + buf * (KT_BUF_WORDS * 4);
        const uint32_t vDst = VtB + buf * (VT_BUF_WORDS * 4);
        #pragma unroll
        for (int i = 0; i < 4; i++) {
            const int row = st_row + i * 16;
            const size_t g = (size_t)(kv0 + row) * D3 + st_c4;
            cp_async16(kDst + (row * 68 + st_c4) * 4, kptr + g);
            cp_async16(vDst + (row * 72 + st_c4) * 4, vptr + g);
        }
    };

    // ---- stage Q (x0.125 exact on tf32 values; no re-rounding needed) ----
    {
        const float* qptr = proj + (size_t)(b * SEQ + q0) * D3 + h * HD;
        #pragma unroll
        for (int i = 0; i < 8; i++) {
            const int f = tid + i * 256;
            const int row = f >> 4;
            const int c4 = (f & 15) << 2;
            float4 v = *(const float4*)(qptr + (size_t)row * D3 + c4);
            float4 t = { v.x * 0.125f, v.y * 0.125f, v.z * 0.125f, v.w * 0.125f };
            *(float4*)(Qs + row * 68 + c4) = t;
        }
    }

    stage_kv(0, 0);
    CP_COMMIT();
    __syncthreads();

    // ---- preload Q fragments ----
    uint32_t qf[8][4];
    #pragma unroll
    for (int ks = 0; ks < 8; ks++) {
        const uint32_t addr = QsB + (wm + (lane & 15)) * 272 + ks * 32 + ((lane >> 4) << 4);
        asm volatile(
            "ldmatrix.sync.aligned.m8n8.x4.shared.b16 {%0,%1,%2,%3}, [%4];"
            : "=r"(qf[ks][0]), "=r"(qf[ks][1]), "=r"(qf[ks][2]), "=r"(qf[ks][3])
            : "r"(addr));
    }

    float o[8][4];
    #pragma unroll
    for (int nt = 0; nt < 8; nt++)
        #pragma unroll
        for (int r = 0; r < 4; r++)
            o[nt][r] = 0.f;
    float m0v = -1e30f, m1v = -1e30f, l0 = 0.f, l1 = 0.f;

    int buf = 0;
    const int NTILES = SEQ / 64;

    // K-fragment ldmatrix lane addressing (rows within nt-pair group)
    const int krow_in = ((lane >> 4) << 3) + (lane & 7);   // 0..15
    const int kchunk  = ((lane >> 3) & 1) << 4;            // 0 or 16 bytes

    for (int t = 0; t < NTILES; ++t) {
        const bool has_next = (t + 1 < NTILES);
        if (has_next) {
            stage_kv(buf ^ 1, (t + 1) * 64);
            CP_COMMIT();
            CP_WAIT(1);
        } else {
            CP_WAIT(0);
        }
        __syncthreads();

        const uint32_t KtBuf = KtB + buf * (KT_BUF_WORDS * 4);
        const uint32_t* Vt = sm + VT_OFF + buf * VT_BUF_WORDS;

        // ---- S = Q K^T (K fragments via ldmatrix.x4) ----
        float s[8][4];
        #pragma unroll
        for (int nt = 0; nt < 8; nt++)
            #pragma unroll
            for (int r = 0; r < 4; r++)
                s[nt][r] = 0.f;

        #pragma unroll
        for (int ks = 0; ks < 8; ks++) {
            #pragma unroll
            for (int ntp = 0; ntp < 4; ntp++) {
                uint32_t kf[4];
                const uint32_t addr = KtBuf + (ntp * 16 + krow_in) * 272 + ks * 32 + kchunk;
                asm volatile(
                    "ldmatrix.sync.aligned.m8n8.x4.shared.b16 {%0,%1,%2,%3}, [%4];"
                    : "=r"(kf[0]), "=r"(kf[1]), "=r"(kf[2]), "=r"(kf[3])
                    : "r"(addr));
                mma_tf32(s[2*ntp][0], s[2*ntp][1], s[2*ntp][2], s[2*ntp][3],
                         qf[ks][0], qf[ks][1], qf[ks][2], qf[ks][3], kf[0], kf[1]);
                mma_tf32(s[2*ntp+1][0], s[2*ntp+1][1], s[2*ntp+1][2], s[2*ntp+1][3],
                         qf[ks][0], qf[ks][1], qf[ks][2], qf[ks][3], kf[2], kf[3]);
            }
        }

        // ---- online softmax ----
        float mx0 = -1e30f, mx1 = -1e30f;
        #pragma unroll
        for (int nt = 0; nt < 8; nt++) {
            mx0 = fmaxf(mx0, fmaxf(s[nt][0], s[nt][1]));
            mx1 = fmaxf(mx1, fmaxf(s[nt][2], s[nt][3]));
        }
        mx0 = fmaxf(mx0, __shfl_xor_sync(0xffffffffu, mx0, 1));
        mx0 = fmaxf(mx0, __shfl_xor_sync(0xffffffffu, mx0, 2));
        mx1 = fmaxf(mx1, __shfl_xor_sync(0xffffffffu, mx1, 1));
        mx1 = fmaxf(mx1, __shfl_xor_sync(0xffffffffu, mx1, 2));

        const float mn0 = fmaxf(m0v, mx0);
        const float mn1 = fmaxf(m1v, mx1);
        const float a0 = __expf(m0v - mn0);
        const float a1 = __expf(m1v - mn1);
        m0v = mn0; m1v = mn1;

        float sum0 = 0.f, sum1 = 0.f;
        #pragma unroll
        for (int nt = 0; nt < 8; nt++) {
            s[nt][0] = __expf(s[nt][0] - mn0);
            s[nt][1] = __expf(s[nt][1] - mn0);
            s[nt][2] = __expf(s[nt][2] - mn1);
            s[nt][3] = __expf(s[nt][3] - mn1);
            sum0 += s[nt][0] + s[nt][1];
            sum1 += s[nt][2] + s[nt][3];
        }
        sum0 += __shfl_xor_sync(0xffffffffu, sum0, 1);
        sum0 += __shfl_xor_sync(0xffffffffu, sum0, 2);
        sum1 += __shfl_xor_sync(0xffffffffu, sum1, 1);
        sum1 += __shfl_xor_sync(0xffffffffu, sum1, 2);
        l0 = l0 * a0 + sum0;
        l1 = l1 * a1 + sum1;

        #pragma unroll
        for (int nt = 0; nt < 8; nt++) {
            o[nt][0] *= a0; o[nt][1] *= a0;
            o[nt][2] *= a1; o[nt][3] *= a1;
        }

        // ---- P to smem (tf32) ----
        {
            const int r = wm + (lane >> 2);
            #pragma unroll
            for (int nt = 0; nt < 8; nt++) {
                uint32_t* p0 = Ps + r * 68 + nt * 8 + ((lane & 3) << 1);
                uint2 t0 = { f2tf32(s[nt][0]), f2tf32(s[nt][1]) };
                *(uint2*)p0 = t0;
                uint2 t1 = { f2tf32(s[nt][2]), f2tf32(s[nt][3]) };
                *(uint2*)(p0 + 8 * 68) = t1;
            }
        }
        __syncwarp();

        // ---- O += P V ----
        #pragma unroll
        for (int ks = 0; ks < 8; ks++) {
            uint32_t pf[4];
            const uint32_t addr = PsB + (wm + (lane & 15)) * 272 + ks * 32 + ((lane >> 4) << 4);
            asm volatile(
                "ldmatrix.sync.aligned.m8n8.x4.shared.b16 {%0,%1,%2,%3}, [%4];"
                : "=r"(pf[0]), "=r"(pf[1]), "=r"(pf[2]), "=r"(pf[3])
                : "r"(addr));
            #pragma unroll
            for (int nt = 0; nt < 8; nt++) {
                const int base = (ks * 8 + (lane & 3)) * 72 + nt * 8 + (lane >> 2);
                const uint32_t b0 = Vt[base];
                const uint32_t b1 = Vt[base + 4 * 72];
                mma_tf32(o[nt][0], o[nt][1], o[nt][2], o[nt][3],
                         pf[0], pf[1], pf[2], pf[3], b0, b1);
            }
        }

        __syncthreads();
        buf ^= 1;
    }

    // ---- epilogue (tf32-rounded for GEMM2's cp.async path) ----
    const float inv0 = 1.f / l0;
    const float inv1 = 1.f / l1;
    const int tok0 = b * SEQ + q0 + wm + (lane >> 2);
    #pragma unroll
    for (int nt = 0; nt < 8; nt++) {
        const int col = h * HD + nt * 8 + ((lane & 3) << 1);
        float2 v0 = { roundtf(o[nt][0] * inv0), roundtf(o[nt][1] * inv0) };
        float2 v1 = { roundtf(o[nt][2] * inv1), roundtf(o[nt][3] * inv1) };
        *(float2*)(ctx + (size_t)tok0 * DMODEL + col) = v0;
        *(float2*)(ctx + (size_t)(tok0 + 8) * DMODEL + col) = v1;
    }
}

// ---------------------------------------------------------------------------
// Launch
// ---------------------------------------------------------------------------
extern "C" void kernel_launch(void* const* d_in, const int* in_sizes, int n_in,
                              void* d_out, int out_size)
{
    const float* qkv   = (const float*)d_in[0];
    const float* W_in  = (const float*)d_in[1];
    const float* b_in  = (const float*)d_in[2];
    const float* W_out = (const float*)d_in[3];
    const float* b_out = (const float*)d_in[4];
    float* out = (float*)d_out;

    static float* p_proj = nullptr;
    static float* p_ctx  = nullptr;
    static float* p_qkv_r = nullptr;
    static float* p_win_r = nullptr;
    static float* p_wout_r = nullptr;
    if (!p_proj) {
        cudaGetSymbolAddress((void**)&p_proj, g_proj);
        cudaGetSymbolAddress((void**)&p_ctx,  g_ctx);
        cudaGetSymbolAddress((void**)&p_qkv_r, g_qkv_r);
        cudaGetSymbolAddress((void**)&p_win_r, g_win_r);
        cudaGetSymbolAddress((void**)&p_wout_r, g_wout_r);
        cudaFuncSetAttribute(tf32_gemm_cp,
                             cudaFuncAttributeMaxDynamicSharedMemorySize, SMEM_BYTES);
        cudaFuncSetAttribute(flash_attn_tc,
                             cudaFuncAttributeMaxDynamicSharedMemorySize, FA_SMEM_BYTES);
    }

    // 0) prepass: round inputs to tf32
    {
        const int n1 = TOKENS * DMODEL / 4;     // qkv
        const int n2 = DMODEL * D3 / 4;         // W_in
        const int n3 = DMODEL * DMODEL / 4;     // W_out
        round_tf32_kernel<<<592, 256>>>((const float4*)qkv, (float4*)p_qkv_r, n1);
        round_tf32_kernel<<<592, 256>>>((const float4*)W_in, (float4*)p_win_r, n2);
        round_tf32_kernel<<<296, 256>>>((const float4*)W_out, (float4*)p_wout_r, n3);
    }

    // 1) proj = qkv @ W_in + b_in   (output tf32-rounded)
    {
        dim3 grid(D3 / 128, TOKENS / 128);
        tf32_gemm_cp<<<grid, 256, SMEM_BYTES>>>(p_qkv_r, p_win_r, b_in, p_proj,
                                                TOKENS, D3, DMODEL, 1);
    }

    // 2) attention -> ctx (output tf32-rounded)
    {
        dim3 grid(SEQ / 128, BATCH * NHEADS);
        flash_attn_tc<<<grid, 256, FA_SMEM_BYTES>>>(p_proj, p_ctx);
    }

    // 3) out = ctx @ W_out + b_out  (fp32 output)
    {
        dim3 grid(DMODEL / 128, TOKENS / 128);
        tf32_gemm_cp<<<grid, 256, SMEM_BYTES>>>(p_ctx, p_wout_r, b_out, out,
                                                TOKENS, DMODEL, DMODEL, 0);
    }
}

// round 12
// speedup vs baseline: 5.2574x; 1.0630x over previous
#include <cuda_runtime.h>
#include <cuda_bf16.h>
#include <cstdint>
#include <cstddef>

// Problem constants
#define BATCH 4
#define SEQ   2048
#define DMODEL 1024
#define NHEADS 16
#define HD     64
#define TOKENS (BATCH * SEQ)          // 8192
#define D3     (3 * DMODEL)           // 3072

// Scratch
__device__ float g_proj [(size_t)TOKENS * D3];     // 96 MB (tf32-rounded)
__device__ float g_ctx  [(size_t)TOKENS * DMODEL]; // 32 MB (tf32-rounded)
__device__ float g_qkv_r[(size_t)TOKENS * DMODEL]; // 32 MB rounded qkv
__device__ float g_win_r[(size_t)DMODEL * D3];     // 12 MB rounded W_in
__device__ float g_wout_r[(size_t)DMODEL * DMODEL];//  4 MB rounded W_out

__device__ __forceinline__ uint32_t f2tf32(float f) {
    uint32_t r;
    asm("cvt.rna.tf32.f32 %0, %1;" : "=r"(r) : "f"(f));
    return r;
}
__device__ __forceinline__ float roundtf(float f) { return __uint_as_float(f2tf32(f)); }

__device__ __forceinline__ void mma_tf32(
    float& c0, float& c1, float& c2, float& c3,
    uint32_t a0, uint32_t a1, uint32_t a2, uint32_t a3,
    uint32_t b0, uint32_t b1)
{
    asm volatile(
        "mma.sync.aligned.m16n8k8.row.col.f32.tf32.tf32.f32 "
        "{%0,%1,%2,%3}, {%4,%5,%6,%7}, {%8,%9}, {%0,%1,%2,%3};\n"
        : "+f"(c0), "+f"(c1), "+f"(c2), "+f"(c3)
        : "r"(a0), "r"(a1), "r"(a2), "r"(a3), "r"(b0), "r"(b1));
}

__device__ __forceinline__ void cp_async16(uint32_t dst, const void* src) {
    asm volatile("cp.async.cg.shared.global [%0], [%1], 16;" :: "r"(dst), "l"(src));
}
#define CP_COMMIT() asm volatile("cp.async.commit_group;")
#define CP_WAIT(n)  asm volatile("cp.async.wait_group %0;" :: "n"(n))

// ---------------------------------------------------------------------------
// Prepass: round fp32 array to tf32 (rna), vectorized.
// ---------------------------------------------------------------------------
__global__ void round_tf32_kernel(const float4* __restrict__ in,
                                  float4* __restrict__ out, int n4)
{
    int i = blockIdx.x * blockDim.x + threadIdx.x;
    const int stride = gridDim.x * blockDim.x;
    for (; i < n4; i += stride) {
        float4 v = in[i];
        float4 r = { roundtf(v.x), roundtf(v.y), roundtf(v.z), roundtf(v.w) };
        out[i] = r;
    }
}

// ---------------------------------------------------------------------------
// TF32 GEMM with cp.async staging (R5-proven). Inputs tf32-rounded.
// 128x128x32 tile, 256 threads, 8 warps (64x32 each), double-buffered.
// ---------------------------------------------------------------------------
#define BSTRIDE 136
#define A_BUF_WORDS (128 * 32)
#define B_BUF_WORDS (32 * BSTRIDE)
#define A_BUF_BYTES (A_BUF_WORDS * 4)
#define B_BUF_BYTES (B_BUF_WORDS * 4)
#define SMEM_BYTES  (2 * (A_BUF_BYTES + B_BUF_BYTES))   // 67584

__global__ __launch_bounds__(256, 2) void tf32_gemm_cp(
    const float* __restrict__ A, const float* __restrict__ B,
    const float* __restrict__ bias, float* __restrict__ C,
    int M, int N, int K, int round_out)
{
    extern __shared__ uint32_t smem[];
    uint32_t* Bs = smem + 2 * A_BUF_WORDS;
    const uint32_t smem_u32 = (uint32_t)__cvta_generic_to_shared(smem);
    const uint32_t bByteBase = smem_u32 + 2 * A_BUF_BYTES;

    const int tid  = threadIdx.x;
    const int lane = tid & 31;
    const int w    = tid >> 5;
    const int wm   = (w & 1) * 64;
    const int wn   = (w >> 1) * 32;
    const int m0   = blockIdx.y * 128;
    const int n0   = blockIdx.x * 128;

    const int a_row = tid >> 3;
    const int a_k4  = tid & 7;
    const int b_k   = tid >> 5;
    const int b_n4  = tid & 31;

    float acc[4][4][4];
    #pragma unroll
    for (int mt = 0; mt < 4; mt++)
        #pragma unroll
        for (int nt = 0; nt < 4; nt++)
            #pragma unroll
            for (int r = 0; r < 4; r++)
                acc[mt][nt][r] = 0.f;

    const int ITERS = K >> 5;

    auto stage = [&](int buf, int k0) {
        const uint32_t aDst = smem_u32 + buf * A_BUF_BYTES;
        #pragma unroll
        for (int i = 0; i < 4; i++) {
            const int row = a_row + i * 32;
            const int dstw = row * 32 + ((a_k4 ^ (row & 7)) << 2);
            cp_async16(aDst + dstw * 4, A + (size_t)(m0 + row) * K + k0 + a_k4 * 4);
        }
        const uint32_t bDst = bByteBase + buf * B_BUF_BYTES;
        #pragma unroll
        for (int i = 0; i < 4; i++) {
            const int k = b_k + i * 8;
            cp_async16(bDst + (k * BSTRIDE + b_n4 * 4) * 4,
                       B + (size_t)(k0 + k) * N + n0 + b_n4 * 4);
        }
    };

    stage(0, 0);
    CP_COMMIT();

    int buf = 0;
    for (int it = 0; it < ITERS; ++it) {
        const bool has_next = (it + 1 < ITERS);
        if (has_next) {
            stage(buf ^ 1, (it + 1) << 5);
            CP_COMMIT();
            CP_WAIT(1);
        } else {
            CP_WAIT(0);
        }
        __syncthreads();

        const uint32_t aBase = smem_u32 + buf * A_BUF_BYTES;
        const uint32_t* BsBuf = Bs + buf * B_BUF_WORDS;

        #pragma unroll
        for (int ks = 0; ks < 4; ks++) {
            uint32_t af[4][4];
            #pragma unroll
            for (int mt = 0; mt < 4; mt++) {
                const int row = wm + mt * 16 + (lane & 15);
                const int c = (ks << 1) + (lane >> 4);
                const uint32_t addr = aBase + row * 128 + ((c ^ (row & 7)) << 4);
                asm volatile(
                    "ldmatrix.sync.aligned.m8n8.x4.shared.b16 {%0,%1,%2,%3}, [%4];"
                    : "=r"(af[mt][0]), "=r"(af[mt][1]), "=r"(af[mt][2]), "=r"(af[mt][3])
                    : "r"(addr));
            }
            uint32_t bf[4][2];
            #pragma unroll
            for (int nt = 0; nt < 4; nt++) {
                const int wrd = ((ks << 3) + (lane & 3)) * BSTRIDE + wn + nt * 8 + (lane >> 2);
                bf[nt][0] = BsBuf[wrd];
                bf[nt][1] = BsBuf[wrd + 4 * BSTRIDE];
            }
            #pragma unroll
            for (int mt = 0; mt < 4; mt++)
                #pragma unroll
                for (int nt = 0; nt < 4; nt++)
                    mma_tf32(acc[mt][nt][0], acc[mt][nt][1], acc[mt][nt][2], acc[mt][nt][3],
                             af[mt][0], af[mt][1], af[mt][2], af[mt][3],
                             bf[nt][0], bf[nt][1]);
        }
        __syncthreads();
        buf ^= 1;
    }

    #pragma unroll
    for (int mt = 0; mt < 4; mt++) {
        const int r0 = m0 + wm + mt * 16 + (lane >> 2);
        const int r1 = r0 + 8;
        #pragma unroll
        for (int nt = 0; nt < 4; nt++) {
            const int col = n0 + wn + nt * 8 + ((lane & 3) << 1);
            const float bx = bias[col], by = bias[col + 1];
            float2 v0 = { acc[mt][nt][0] + bx, acc[mt][nt][1] + by };
            float2 v1 = { acc[mt][nt][2] + bx, acc[mt][nt][3] + by };
            if (round_out) {
                v0.x = roundtf(v0.x); v0.y = roundtf(v0.y);
                v1.x = roundtf(v1.x); v1.y = roundtf(v1.y);
            }
            *(float2*)(C + (size_t)r0 * N + col) = v0;
            *(float2*)(C + (size_t)r1 * N + col) = v1;
        }
    }
}

// ---------------------------------------------------------------------------
// Tensor-core flash attention (R5 structure, 256 threads, 128 Q rows).
// Smem shrunk to 106,496 B by ALIASING Ps onto Qs (Qs is dead after the
// Q-fragment preload; the first in-loop __syncthreads orders preload reads
// before the first P store). -> 2 CTAs/SM = 16 warps/SM.
// ---------------------------------------------------------------------------
#define QS_OFF 0
#define PS_OFF 0                                     // aliased with Qs
#define KT_OFF 8704                                  // 128*68
#define KT_BUF_WORDS (64 * 68)                       // 4352
#define VT_OFF (KT_OFF + 2 * KT_BUF_WORDS)           // 17408
#define VT_BUF_WORDS (64 * 72)                       // 4608
#define FA_SMEM_WORDS (VT_OFF + 2 * VT_BUF_WORDS)    // 26624
#define FA_SMEM_BYTES (FA_SMEM_WORDS * 4)            // 106496

__global__ __launch_bounds__(256, 2) void flash_attn_tc(
    const float* __restrict__ proj, float* __restrict__ ctx)
{
    extern __shared__ uint32_t sm[];
    uint32_t* Qs = sm + QS_OFF;
    uint32_t* Ps = sm + PS_OFF;                      // same region as Qs
    const uint32_t smem_u32 = (uint32_t)__cvta_generic_to_shared(sm);
    const uint32_t QsB = smem_u32 + QS_OFF * 4;
    const uint32_t PsB = smem_u32 + PS_OFF * 4;
    const uint32_t KtB = smem_u32 + KT_OFF * 4;
    const uint32_t VtB = smem_u32 + VT_OFF * 4;

    const int tid  = threadIdx.x;
    const int lane = tid & 31;
    const int w    = tid >> 5;
    const int wm   = w * 16;
    const int b    = blockIdx.y >> 4;
    const int h    = blockIdx.y & 15;
    const int q0   = blockIdx.x * 128;

    const float* kptr = proj + (size_t)b * SEQ * D3 + DMODEL + h * HD;
    const float* vptr = kptr + DMODEL;

    const int st_row = tid >> 4;
    const int st_c4  = (tid & 15) << 2;

    auto stage_kv = [&](int buf, int kv0) {
        const uint32_t kDst = KtB + buf * (KT_BUF_WORDS * 4);
        const uint32_t vDst = VtB + buf * (VT_BUF_WORDS * 4);
        #pragma unroll
        for (int i = 0; i < 4; i++) {
            const int row = st_row + i * 16;
            const size_t g = (size_t)(kv0 + row) * D3 + st_c4;
            cp_async16(kDst + (row * 68 + st_c4) * 4, kptr + g);
            cp_async16(vDst + (row * 72 + st_c4) * 4, vptr + g);
        }
    };

    // ---- stage Q (x0.125 exact on tf32 values) ----
    {
        const float* qptr = proj + (size_t)(b * SEQ + q0) * D3 + h * HD;
        #pragma unroll
        for (int i = 0; i < 8; i++) {
            const int f = tid + i * 256;
            const int row = f >> 4;
            const int c4 = (f & 15) << 2;
            float4 v = *(const float4*)(qptr + (size_t)row * D3 + c4);
            float4 t = { v.x * 0.125f, v.y * 0.125f, v.z * 0.125f, v.w * 0.125f };
            *(float4*)(Qs + row * 68 + c4) = t;
        }
    }

    stage_kv(0, 0);
    CP_COMMIT();
    __syncthreads();

    // ---- preload Q fragments (after this, Qs region is dead -> reused as Ps) ----
    uint32_t qf[8][4];
    #pragma unroll
    for (int ks = 0; ks < 8; ks++) {
        const uint32_t addr = QsB + (wm + (lane & 15)) * 272 + ks * 32 + ((lane >> 4) << 4);
        asm volatile(
            "ldmatrix.sync.aligned.m8n8.x4.shared.b16 {%0,%1,%2,%3}, [%4];"
            : "=r"(qf[ks][0]), "=r"(qf[ks][1]), "=r"(qf[ks][2]), "=r"(qf[ks][3])
            : "r"(addr));
    }

    float o[8][4];
    #pragma unroll
    for (int nt = 0; nt < 8; nt++)
        #pragma unroll
        for (int r = 0; r < 4; r++)
            o[nt][r] = 0.f;
    float m0v = -1e30f, m1v = -1e30f, l0 = 0.f, l1 = 0.f;

    int buf = 0;
    const int NTILES = SEQ / 64;

    const int krow_in = ((lane >> 4) << 3) + (lane & 7);
    const int kchunk  = ((lane >> 3) & 1) << 4;

    for (int t = 0; t < NTILES; ++t) {
        const bool has_next = (t + 1 < NTILES);
        if (has_next) {
            stage_kv(buf ^ 1, (t + 1) * 64);
            CP_COMMIT();
            CP_WAIT(1);
        } else {
            CP_WAIT(0);
        }
        __syncthreads();   // KV ready; also orders Q preload reads before P stores (t=0)

        const uint32_t KtBuf = KtB + buf * (KT_BUF_WORDS * 4);
        const uint32_t* Vt = sm + VT_OFF + buf * VT_BUF_WORDS;

        // ---- S = Q K^T ----
        float s[8][4];
        #pragma unroll
        for (int nt = 0; nt < 8; nt++)
            #pragma unroll
            for (int r = 0; r < 4; r++)
                s[nt][r] = 0.f;

        #pragma unroll
        for (int ks = 0; ks < 8; ks++) {
            #pragma unroll
            for (int ntp = 0; ntp < 4; ntp++) {
                uint32_t kf[4];
                const uint32_t addr = KtBuf + (ntp * 16 + krow_in) * 272 + ks * 32 + kchunk;
                asm volatile(
                    "ldmatrix.sync.aligned.m8n8.x4.shared.b16 {%0,%1,%2,%3}, [%4];"
                    : "=r"(kf[0]), "=r"(kf[1]), "=r"(kf[2]), "=r"(kf[3])
                    : "r"(addr));
                mma_tf32(s[2*ntp][0], s[2*ntp][1], s[2*ntp][2], s[2*ntp][3],
                         qf[ks][0], qf[ks][1], qf[ks][2], qf[ks][3], kf[0], kf[1]);
                mma_tf32(s[2*ntp+1][0], s[2*ntp+1][1], s[2*ntp+1][2], s[2*ntp+1][3],
                         qf[ks][0], qf[ks][1], qf[ks][2], qf[ks][3], kf[2], kf[3]);
            }
        }

        // ---- online softmax ----
        float mx0 = -1e30f, mx1 = -1e30f;
        #pragma unroll
        for (int nt = 0; nt < 8; nt++) {
            mx0 = fmaxf(mx0, fmaxf(s[nt][0], s[nt][1]));
            mx1 = fmaxf(mx1, fmaxf(s[nt][2], s[nt][3]));
        }
        mx0 = fmaxf(mx0, __shfl_xor_sync(0xffffffffu, mx0, 1));
        mx0 = fmaxf(mx0, __shfl_xor_sync(0xffffffffu, mx0, 2));
        mx1 = fmaxf(mx1, __shfl_xor_sync(0xffffffffu, mx1, 1));
        mx1 = fmaxf(mx1, __shfl_xor_sync(0xffffffffu, mx1, 2));

        const float mn0 = fmaxf(m0v, mx0);
        const float mn1 = fmaxf(m1v, mx1);
        const float a0 = __expf(m0v - mn0);
        const float a1 = __expf(m1v - mn1);
        m0v = mn0; m1v = mn1;

        float sum0 = 0.f, sum1 = 0.f;
        #pragma unroll
        for (int nt = 0; nt < 8; nt++) {
            s[nt][0] = __expf(s[nt][0] - mn0);
            s[nt][1] = __expf(s[nt][1] - mn0);
            s[nt][2] = __expf(s[nt][2] - mn1);
            s[nt][3] = __expf(s[nt][3] - mn1);
            sum0 += s[nt][0] + s[nt][1];
            sum1 += s[nt][2] + s[nt][3];
        }
        sum0 += __shfl_xor_sync(0xffffffffu, sum0, 1);
        sum0 += __shfl_xor_sync(0xffffffffu, sum0, 2);
        sum1 += __shfl_xor_sync(0xffffffffu, sum1, 1);
        sum1 += __shfl_xor_sync(0xffffffffu, sum1, 2);
        l0 = l0 * a0 + sum0;
        l1 = l1 * a1 + sum1;

        #pragma unroll
        for (int nt = 0; nt < 8; nt++) {
            o[nt][0] *= a0; o[nt][1] *= a0;
            o[nt][2] *= a1; o[nt][3] *= a1;
        }

        // ---- P to smem (tf32) — region aliased with Qs ----
        {
            const int r = wm + (lane >> 2);
            #pragma unroll
            for (int nt = 0; nt < 8; nt++) {
                uint32_t* p0 = Ps + r * 68 + nt * 8 + ((lane & 3) << 1);
                uint2 t0 = { f2tf32(s[nt][0]), f2tf32(s[nt][1]) };
                *(uint2*)p0 = t0;
                uint2 t1 = { f2tf32(s[nt][2]), f2tf32(s[nt][3]) };
                *(uint2*)(p0 + 8 * 68) = t1;
            }
        }
        __syncwarp();

        // ---- O += P V ----
        #pragma unroll
        for (int ks = 0; ks < 8; ks++) {
            uint32_t pf[4];
            const uint32_t addr = PsB + (wm + (lane & 15)) * 272 + ks * 32 + ((lane >> 4) << 4);
            asm volatile(
                "ldmatrix.sync.aligned.m8n8.x4.shared.b16 {%0,%1,%2,%3}, [%4];"
                : "=r"(pf[0]), "=r"(pf[1]), "=r"(pf[2]), "=r"(pf[3])
                : "r"(addr));
            #pragma unroll
            for (int nt = 0; nt < 8; nt++) {
                const int base = (ks * 8 + (lane & 3)) * 72 + nt * 8 + (lane >> 2);
                const uint32_t b0 = Vt[base];
                const uint32_t b1 = Vt[base + 4 * 72];
                mma_tf32(o[nt][0], o[nt][1], o[nt][2], o[nt][3],
                         pf[0], pf[1], pf[2], pf[3], b0, b1);
            }
        }

        __syncthreads();
        buf ^= 1;
    }

    // ---- epilogue ----
    const float inv0 = 1.f / l0;
    const float inv1 = 1.f / l1;
    const int tok0 = b * SEQ + q0 + wm + (lane >> 2);
    #pragma unroll
    for (int nt = 0; nt < 8; nt++) {
        const int col = h * HD + nt * 8 + ((lane & 3) << 1);
        float2 v0 = { roundtf(o[nt][0] * inv0), roundtf(o[nt][1] * inv0) };
        float2 v1 = { roundtf(o[nt][2] * inv1), roundtf(o[nt][3] * inv1) };
        *(float2*)(ctx + (size_t)tok0 * DMODEL + col) = v0;
        *(float2*)(ctx + (size_t)(tok0 + 8) * DMODEL + col) = v1;
    }
}

// ---------------------------------------------------------------------------
// Launch
// ---------------------------------------------------------------------------
extern "C" void kernel_launch(void* const* d_in, const int* in_sizes, int n_in,
                              void* d_out, int out_size)
{
    const float* qkv   = (const float*)d_in[0];
    const float* W_in  = (const float*)d_in[1];
    const float* b_in  = (const float*)d_in[2];
    const float* W_out = (const float*)d_in[3];
    const float* b_out = (const float*)d_in[4];
    float* out = (float*)d_out;

    static float* p_proj = nullptr;
    static float* p_ctx  = nullptr;
    static float* p_qkv_r = nullptr;
    static float* p_win_r = nullptr;
    static float* p_wout_r = nullptr;
    if (!p_proj) {
        cudaGetSymbolAddress((void**)&p_proj, g_proj);
        cudaGetSymbolAddress((void**)&p_ctx,  g_ctx);
        cudaGetSymbolAddress((void**)&p_qkv_r, g_qkv_r);
        cudaGetSymbolAddress((void**)&p_win_r, g_win_r);
        cudaGetSymbolAddress((void**)&p_wout_r, g_wout_r);
        cudaFuncSetAttribute(tf32_gemm_cp,
                             cudaFuncAttributeMaxDynamicSharedMemorySize, SMEM_BYTES);
        cudaFuncSetAttribute(flash_attn_tc,
                             cudaFuncAttributeMaxDynamicSharedMemorySize, FA_SMEM_BYTES);
    }

    // 0) prepass: round inputs to tf32
    round_tf32_kernel<<<592, 256>>>((const float4*)qkv, (float4*)p_qkv_r,
                                    TOKENS * DMODEL / 4);
    round_tf32_kernel<<<592, 256>>>((const float4*)W_in, (float4*)p_win_r,
                                    DMODEL * D3 / 4);
    round_tf32_kernel<<<296, 256>>>((const float4*)W_out, (float4*)p_wout_r,
                                    DMODEL * DMODEL / 4);

    // 1) proj = qkv @ W_in + b_in   (output tf32-rounded)
    {
        dim3 grid(D3 / 128, TOKENS / 128);
        tf32_gemm_cp<<<grid, 256, SMEM_BYTES>>>(p_qkv_r, p_win_r, b_in, p_proj,
                                                TOKENS, D3, DMODEL, 1);
    }

    // 2) attention -> ctx (128 Q rows / CTA, 256 threads, 2 CTAs/SM)
    {
        dim3 grid(SEQ / 128, BATCH * NHEADS);   // 16 x 64
        flash_attn_tc<<<grid, 256, FA_SMEM_BYTES>>>(p_proj, p_ctx);
    }

    // 3) out = ctx @ W_out + b_out  (fp32 output)
    {
        dim3 grid(DMODEL / 128, TOKENS / 128);
        tf32_gemm_cp<<<grid, 256, SMEM_BYTES>>>(p_ctx, p_wout_r, b_out, out,
                                                TOKENS, DMODEL, DMODEL, 0);
    }
}

// round 13
// speedup vs baseline: 5.4183x; 1.0306x over previous
#include <cuda_runtime.h>
#include <cuda_bf16.h>
#include <cstdint>
#include <cstddef>

// Problem constants
#define BATCH 4
#define SEQ   2048
#define DMODEL 1024
#define NHEADS 16
#define HD     64
#define TOKENS (BATCH * SEQ)          // 8192
#define D3     (3 * DMODEL)           // 3072

// Scratch
__device__ float g_proj [(size_t)TOKENS * D3];      // 96 MB (tf32-rounded)
__device__ float g_ctx  [(size_t)TOKENS * DMODEL];  // 32 MB (tf32-rounded)
__device__ float g_winT [(size_t)D3 * DMODEL];      // 12 MB rounded W_in^T  [3072][1024]
__device__ float g_woutT[(size_t)DMODEL * DMODEL];  //  4 MB rounded W_out^T [1024][1024]

__device__ __forceinline__ uint32_t f2tf32(float f) {
    uint32_t r;
    asm("cvt.rna.tf32.f32 %0, %1;" : "=r"(r) : "f"(f));
    return r;
}
__device__ __forceinline__ float roundtf(float f) { return __uint_as_float(f2tf32(f)); }

__device__ __forceinline__ void mma_tf32(
    float& c0, float& c1, float& c2, float& c3,
    uint32_t a0, uint32_t a1, uint32_t a2, uint32_t a3,
    uint32_t b0, uint32_t b1)
{
    asm volatile(
        "mma.sync.aligned.m16n8k8.row.col.f32.tf32.tf32.f32 "
        "{%0,%1,%2,%3}, {%4,%5,%6,%7}, {%8,%9}, {%0,%1,%2,%3};\n"
        : "+f"(c0), "+f"(c1), "+f"(c2), "+f"(c3)
        : "r"(a0), "r"(a1), "r"(a2), "r"(a3), "r"(b0), "r"(b1));
}

__device__ __forceinline__ void cp_async16(uint32_t dst, const void* src) {
    asm volatile("cp.async.cg.shared.global [%0], [%1], 16;" :: "r"(dst), "l"(src));
}
#define CP_COMMIT() asm volatile("cp.async.commit_group;")
#define CP_WAIT(n)  asm volatile("cp.async.wait_group %0;" :: "n"(n))

// ---------------------------------------------------------------------------
// Prepass: out[n][k] = round_tf32(in[k][n]);  in: [K][N], out: [N][K]
// ---------------------------------------------------------------------------
__global__ __launch_bounds__(256) void round_transpose_kernel(
    const float* __restrict__ in, float* __restrict__ out, int K, int N)
{
    __shared__ float t[32][33];
    const int k0 = blockIdx.y * 32;
    const int n0 = blockIdx.x * 32;
    const int tx = threadIdx.x & 31;
    const int ty = threadIdx.x >> 5;   // 0..7
    #pragma unroll
    for (int i = 0; i < 4; i++)
        t[ty + i * 8][tx] = in[(size_t)(k0 + ty + i * 8) * N + n0 + tx];
    __syncthreads();
    #pragma unroll
    for (int i = 0; i < 4; i++)
        out[(size_t)(n0 + ty + i * 8) * K + k0 + tx] = roundtf(t[tx][ty + i * 8]);
}

// ---------------------------------------------------------------------------
// TF32 NT GEMM: C[M,N] = A[M,K] @ Bt[N,K]^T + bias[N]
// Both operands staged identically ([128 rows][32 floats], SW128 swizzle),
// both fetched via ldmatrix.x4. 3-stage cp.async ring, ONE syncthreads/iter.
// 128x128x32 tile, 256 threads, 8 warps (64x32 each).
// A may be raw fp32 (HW truncates to tf32); Bt must be pre-rounded.
// ---------------------------------------------------------------------------
#define OP_BYTES   16384                       // 128 rows x 128 B
#define STG_BYTES  (2 * OP_BYTES)              // A + B per stage
#define NT_SMEM_BYTES (3 * STG_BYTES)          // 98304

__global__ __launch_bounds__(256, 2) void tf32_gemm_nt(
    const float* __restrict__ A, const float* __restrict__ Bt,
    const float* __restrict__ bias, float* __restrict__ C,
    int Ntot, int K, int round_out)
{
    extern __shared__ uint32_t smem[];
    const uint32_t smem_u32 = (uint32_t)__cvta_generic_to_shared(smem);

    const int tid  = threadIdx.x;
    const int lane = tid & 31;
    const int w    = tid >> 5;
    const int wm   = (w & 1) * 64;
    const int wn   = (w >> 1) * 32;
    const int m0   = blockIdx.y * 128;
    const int n0   = blockIdx.x * 128;

    // staging map: 128 rows x 8 chunks, 256 threads -> 4 rows each per operand
    const int r0 = tid >> 3;       // 0..31
    const int ch = tid & 7;        // 16B chunk

    // B-fragment ldmatrix lane map (attention-validated)
    const int krow_in = ((lane >> 4) << 3) + (lane & 7);   // 0..15
    const int kbit    = (lane >> 3) & 1;                   // k-half chunk bit

    float acc[4][4][4];
    #pragma unroll
    for (int mt = 0; mt < 4; mt++)
        #pragma unroll
        for (int nt = 0; nt < 4; nt++)
            #pragma unroll
            for (int r = 0; r < 4; r++)
                acc[mt][nt][r] = 0.f;

    const int ITERS = K >> 5;   // 32

    auto stage = [&](int s, int k0) {
        const uint32_t aDst = smem_u32 + s * STG_BYTES;
        const uint32_t bDst = aDst + OP_BYTES;
        #pragma unroll
        for (int i = 0; i < 4; i++) {
            const int row = r0 + i * 32;
            const uint32_t off = row * 128 + ((ch ^ (row & 7)) << 4);
            cp_async16(aDst + off, A  + (size_t)(m0 + row) * K + k0 + ch * 4);
            cp_async16(bDst + off, Bt + (size_t)(n0 + row) * K + k0 + ch * 4);
        }
    };

    stage(0, 0);  CP_COMMIT();
    stage(1, 32); CP_COMMIT();

    for (int it = 0; it < ITERS; ++it) {
        if (it + 1 < ITERS) { CP_WAIT(1); } else { CP_WAIT(0); }
        __syncthreads();

        const uint32_t aBase = smem_u32 + (it % 3) * STG_BYTES;
        const uint32_t bBase = aBase + OP_BYTES;

        #pragma unroll
        for (int ks = 0; ks < 4; ks++) {
            uint32_t af[4][4];
            #pragma unroll
            for (int mt = 0; mt < 4; mt++) {
                const int row = wm + mt * 16 + (lane & 15);
                const int c = (ks << 1) + (lane >> 4);
                const uint32_t addr = aBase + row * 128 + ((c ^ (row & 7)) << 4);
                asm volatile(
                    "ldmatrix.sync.aligned.m8n8.x4.shared.b16 {%0,%1,%2,%3}, [%4];"
                    : "=r"(af[mt][0]), "=r"(af[mt][1]), "=r"(af[mt][2]), "=r"(af[mt][3])
                    : "r"(addr));
            }
            uint32_t bf[2][4];
            #pragma unroll
            for (int ntp = 0; ntp < 2; ntp++) {
                const int row = wn + ntp * 16 + krow_in;
                const int c = (ks << 1) + kbit;
                const uint32_t addr = bBase + row * 128 + ((c ^ (row & 7)) << 4);
                asm volatile(
                    "ldmatrix.sync.aligned.m8n8.x4.shared.b16 {%0,%1,%2,%3}, [%4];"
                    : "=r"(bf[ntp][0]), "=r"(bf[ntp][1]), "=r"(bf[ntp][2]), "=r"(bf[ntp][3])
                    : "r"(addr));
            }
            #pragma unroll
            for (int mt = 0; mt < 4; mt++)
                #pragma unroll
                for (int ntp = 0; ntp < 2; ntp++) {
                    mma_tf32(acc[mt][2*ntp][0], acc[mt][2*ntp][1],
                             acc[mt][2*ntp][2], acc[mt][2*ntp][3],
                             af[mt][0], af[mt][1], af[mt][2], af[mt][3],
                             bf[ntp][0], bf[ntp][1]);
                    mma_tf32(acc[mt][2*ntp+1][0], acc[mt][2*ntp+1][1],
                             acc[mt][2*ntp+1][2], acc[mt][2*ntp+1][3],
                             af[mt][0], af[mt][1], af[mt][2], af[mt][3],
                             bf[ntp][2], bf[ntp][3]);
                }
        }

        if (it + 2 < ITERS) {
            stage((it + 2) % 3, (it + 2) << 5);
            CP_COMMIT();
        }
    }

    // epilogue: bias + optional tf32 rounding
    #pragma unroll
    for (int mt = 0; mt < 4; mt++) {
        const int r0o = m0 + wm + mt * 16 + (lane >> 2);
        const int r1o = r0o + 8;
        #pragma unroll
        for (int nt = 0; nt < 4; nt++) {
            const int col = n0 + wn + nt * 8 + ((lane & 3) << 1);
            const float bx = bias[col], by = bias[col + 1];
            float2 v0 = { acc[mt][nt][0] + bx, acc[mt][nt][1] + by };
            float2 v1 = { acc[mt][nt][2] + bx, acc[mt][nt][3] + by };
            if (round_out) {
                v0.x = roundtf(v0.x); v0.y = roundtf(v0.y);
                v1.x = roundtf(v1.x); v1.y = roundtf(v1.y);
            }
            *(float2*)(C + (size_t)r0o * Ntot + col) = v0;
            *(float2*)(C + (size_t)r1o * Ntot + col) = v1;
        }
    }
}

// ---------------------------------------------------------------------------
// Tensor-core flash attention (R12-proven, unchanged): 256 threads, 128 Q rows,
// Ps aliased onto Qs -> 106,496 B smem -> 2 CTAs/SM.
// ---------------------------------------------------------------------------
#define QS_OFF 0
#define PS_OFF 0                                     // aliased with Qs
#define KT_OFF 8704                                  // 128*68
#define KT_BUF_WORDS (64 * 68)                       // 4352
#define VT_OFF (KT_OFF + 2 * KT_BUF_WORDS)           // 17408
#define VT_BUF_WORDS (64 * 72)                       // 4608
#define FA_SMEM_WORDS (VT_OFF + 2 * VT_BUF_WORDS)    // 26624
#define FA_SMEM_BYTES (FA_SMEM_WORDS * 4)            // 106496

__global__ __launch_bounds__(256, 2) void flash_attn_tc(
    const float* __restrict__ proj, float* __restrict__ ctx)
{
    extern __shared__ uint32_t sm[];
    uint32_t* Qs = sm + QS_OFF;
    uint32_t* Ps = sm + PS_OFF;                      // same region as Qs
    const uint32_t smem_u32 = (uint32_t)__cvta_generic_to_shared(sm);
    const uint32_t QsB = smem_u32 + QS_OFF * 4;
    const uint32_t PsB = smem_u32 + PS_OFF * 4;
    const uint32_t KtB = smem_u32 + KT_OFF * 4;
    const uint32_t VtB = smem_u32 + VT_OFF * 4;

    const int tid  = threadIdx.x;
    const int lane = tid & 31;
    const int w    = tid >> 5;
    const int wm   = w * 16;
    const int b    = blockIdx.y >> 4;
    const int h    = blockIdx.y & 15;
    const int q0   = blockIdx.x * 128;

    const float* kptr = proj + (size_t)b * SEQ * D3 + DMODEL + h * HD;
    const float* vptr = kptr + DMODEL;

    const int st_row = tid >> 4;
    const int st_c4  = (tid & 15) << 2;

    auto stage_kv = [&](int buf, int kv0) {
        const uint32_t kDst = KtB + buf * (KT_BUF_WORDS * 4);
        const uint32_t vDst = VtB + buf * (VT_BUF_WORDS * 4);
        #pragma unroll
        for (int i = 0; i < 4; i++) {
            const int row = st_row + i * 16;
            const size_t g = (size_t)(kv0 + row) * D3 + st_c4;
            cp_async16(kDst + (row * 68 + st_c4) * 4, kptr + g);
            cp_async16(vDst + (row * 72 + st_c4) * 4, vptr + g);
        }
    };

    // ---- stage Q (x0.125 exact on tf32 values) ----
    {
        const float* qptr = proj + (size_t)(b * SEQ + q0) * D3 + h * HD;
        #pragma unroll
        for (int i = 0; i < 8; i++) {
            const int f = tid + i * 256;
            const int row = f >> 4;
            const int c4 = (f & 15) << 2;
            float4 v = *(const float4*)(qptr + (size_t)row * D3 + c4);
            float4 t = { v.x * 0.125f, v.y * 0.125f, v.z * 0.125f, v.w * 0.125f };
            *(float4*)(Qs + row * 68 + c4) = t;
        }
    }

    stage_kv(0, 0);
    CP_COMMIT();
    __syncthreads();

    // ---- preload Q fragments (Qs dead afterwards; reused as Ps) ----
    uint32_t qf[8][4];
    #pragma unroll
    for (int ks = 0; ks < 8; ks++) {
        const uint32_t addr = QsB + (wm + (lane & 15)) * 272 + ks * 32 + ((lane >> 4) << 4);
        asm volatile(
            "ldmatrix.sync.aligned.m8n8.x4.shared.b16 {%0,%1,%2,%3}, [%4];"
            : "=r"(qf[ks][0]), "=r"(qf[ks][1]), "=r"(qf[ks][2]), "=r"(qf[ks][3])
            : "r"(addr));
    }

    float o[8][4];
    #pragma unroll
    for (int nt = 0; nt < 8; nt++)
        #pragma unroll
        for (int r = 0; r < 4; r++)
            o[nt][r] = 0.f;
    float m0v = -1e30f, m1v = -1e30f, l0 = 0.f, l1 = 0.f;

    int buf = 0;
    const int NTILES = SEQ / 64;

    const int krow_in = ((lane >> 4) << 3) + (lane & 7);
    const int kchunk  = ((lane >> 3) & 1) << 4;

    for (int t = 0; t < NTILES; ++t) {
        const bool has_next = (t + 1 < NTILES);
        if (has_next) {
            stage_kv(buf ^ 1, (t + 1) * 64);
            CP_COMMIT();
            CP_WAIT(1);
        } else {
            CP_WAIT(0);
        }
        __syncthreads();   // KV ready; also orders Q preload reads before P stores (t=0)

        const uint32_t KtBuf = KtB + buf * (KT_BUF_WORDS * 4);
        const uint32_t* Vt = sm + VT_OFF + buf * VT_BUF_WORDS;

        // ---- S = Q K^T ----
        float s[8][4];
        #pragma unroll
        for (int nt = 0; nt < 8; nt++)
            #pragma unroll
            for (int r = 0; r < 4; r++)
                s[nt][r] = 0.f;

        #pragma unroll
        for (int ks = 0; ks < 8; ks++) {
            #pragma unroll
            for (int ntp = 0; ntp < 4; ntp++) {
                uint32_t kf[4];
                const uint32_t addr = KtBuf + (ntp * 16 + krow_in) * 272 + ks * 32 + kchunk;
                asm volatile(
                    "ldmatrix.sync.aligned.m8n8.x4.shared.b16 {%0,%1,%2,%3}, [%4];"
                    : "=r"(kf[0]), "=r"(kf[1]), "=r"(kf[2]), "=r"(kf[3])
                    : "r"(addr));
                mma_tf32(s[2*ntp][0], s[2*ntp][1], s[2*ntp][2], s[2*ntp][3],
                         qf[ks][0], qf[ks][1], qf[ks][2], qf[ks][3], kf[0], kf[1]);
                mma_tf32(s[2*ntp+1][0], s[2*ntp+1][1], s[2*ntp+1][2], s[2*ntp+1][3],
                         qf[ks][0], qf[ks][1], qf[ks][2], qf[ks][3], kf[2], kf[3]);
            }
        }

        // ---- online softmax ----
        float mx0 = -1e30f, mx1 = -1e30f;
        #pragma unroll
        for (int nt = 0; nt < 8; nt++) {
            mx0 = fmaxf(mx0, fmaxf(s[nt][0], s[nt][1]));
            mx1 = fmaxf(mx1, fmaxf(s[nt][2], s[nt][3]));
        }
        mx0 = fmaxf(mx0, __shfl_xor_sync(0xffffffffu, mx0, 1));
        mx0 = fmaxf(mx0, __shfl_xor_sync(0xffffffffu, mx0, 2));
        mx1 = fmaxf(mx1, __shfl_xor_sync(0xffffffffu, mx1, 1));
        mx1 = fmaxf(mx1, __shfl_xor_sync(0xffffffffu, mx1, 2));

        const float mn0 = fmaxf(m0v, mx0);
        const float mn1 = fmaxf(m1v, mx1);
        const float a0 = __expf(m0v - mn0);
        const float a1 = __expf(m1v - mn1);
        m0v = mn0; m1v = mn1;

        float sum0 = 0.f, sum1 = 0.f;
        #pragma unroll
        for (int nt = 0; nt < 8; nt++) {
            s[nt][0] = __expf(s[nt][0] - mn0);
            s[nt][1] = __expf(s[nt][1] - mn0);
            s[nt][2] = __expf(s[nt][2] - mn1);
            s[nt][3] = __expf(s[nt][3] - mn1);
            sum0 += s[nt][0] + s[nt][1];
            sum1 += s[nt][2] + s[nt][3];
        }
        sum0 += __shfl_xor_sync(0xffffffffu, sum0, 1);
        sum0 += __shfl_xor_sync(0xffffffffu, sum0, 2);
        sum1 += __shfl_xor_sync(0xffffffffu, sum1, 1);
        sum1 += __shfl_xor_sync(0xffffffffu, sum1, 2);
        l0 = l0 * a0 + sum0;
        l1 = l1 * a1 + sum1;

        #pragma unroll
        for (int nt = 0; nt < 8; nt++) {
            o[nt][0] *= a0; o[nt][1] *= a0;
            o[nt][2] *= a1; o[nt][3] *= a1;
        }

        // ---- P to smem (tf32) — region aliased with Qs ----
        {
            const int r = wm + (lane >> 2);
            #pragma unroll
            for (int nt = 0; nt < 8; nt++) {
                uint32_t* p0 = Ps + r * 68 + nt * 8 + ((lane & 3) << 1);
                uint2 t0 = { f2tf32(s[nt][0]), f2tf32(s[nt][1]) };
                *(uint2*)p0 = t0;
                uint2 t1 = { f2tf32(s[nt][2]), f2tf32(s[nt][3]) };
                *(uint2*)(p0 + 8 * 68) = t1;
            }
        }
        __syncwarp();

        // ---- O += P V ----
        #pragma unroll
        for (int ks = 0; ks < 8; ks++) {
            uint32_t pf[4];
            const uint32_t addr = PsB + (wm + (lane & 15)) * 272 + ks * 32 + ((lane >> 4) << 4);
            asm volatile(
                "ldmatrix.sync.aligned.m8n8.x4.shared.b16 {%0,%1,%2,%3}, [%4];"
                : "=r"(pf[0]), "=r"(pf[1]), "=r"(pf[2]), "=r"(pf[3])
                : "r"(addr));
            #pragma unroll
            for (int nt = 0; nt < 8; nt++) {
                const int base = (ks * 8 + (lane & 3)) * 72 + nt * 8 + (lane >> 2);
                const uint32_t b0 = Vt[base];
                const uint32_t b1 = Vt[base + 4 * 72];
                mma_tf32(o[nt][0], o[nt][1], o[nt][2], o[nt][3],
                         pf[0], pf[1], pf[2], pf[3], b0, b1);
            }
        }

        __syncthreads();
        buf ^= 1;
    }

    // ---- epilogue ----
    const float inv0 = 1.f / l0;
    const float inv1 = 1.f / l1;
    const int tok0 = b * SEQ + q0 + wm + (lane >> 2);
    #pragma unroll
    for (int nt = 0; nt < 8; nt++) {
        const int col = h * HD + nt * 8 + ((lane & 3) << 1);
        float2 v0 = { roundtf(o[nt][0] * inv0), roundtf(o[nt][1] * inv0) };
        float2 v1 = { roundtf(o[nt][2] * inv1), roundtf(o[nt][3] * inv1) };
        *(float2*)(ctx + (size_t)tok0 * DMODEL + col) = v0;
        *(float2*)(ctx + (size_t)(tok0 + 8) * DMODEL + col) = v1;
    }
}

// ---------------------------------------------------------------------------
// Launch
// ---------------------------------------------------------------------------
extern "C" void kernel_launch(void* const* d_in, const int* in_sizes, int n_in,
                              void* d_out, int out_size)
{
    const float* qkv   = (const float*)d_in[0];
    const float* W_in  = (const float*)d_in[1];
    const float* b_in  = (const float*)d_in[2];
    const float* W_out = (const float*)d_in[3];
    const float* b_out = (const float*)d_in[4];
    float* out = (float*)d_out;

    static float* p_proj = nullptr;
    static float* p_ctx  = nullptr;
    static float* p_winT = nullptr;
    static float* p_woutT = nullptr;
    if (!p_proj) {
        cudaGetSymbolAddress((void**)&p_proj, g_proj);
        cudaGetSymbolAddress((void**)&p_ctx,  g_ctx);
        cudaGetSymbolAddress((void**)&p_winT, g_winT);
        cudaGetSymbolAddress((void**)&p_woutT, g_woutT);
        cudaFuncSetAttribute(tf32_gemm_nt,
                             cudaFuncAttributeMaxDynamicSharedMemorySize, NT_SMEM_BYTES);
        cudaFuncSetAttribute(flash_attn_tc,
                             cudaFuncAttributeMaxDynamicSharedMemorySize, FA_SMEM_BYTES);
    }

    // 0) prepass: round+transpose weights only (qkv fed raw; HMMA truncates A)
    {
        dim3 g1(D3 / 32, DMODEL / 32);      // W_in [1024][3072] -> [3072][1024]
        round_transpose_kernel<<<g1, 256>>>(W_in, p_winT, DMODEL, D3);
        dim3 g2(DMODEL / 32, DMODEL / 32);  // W_out
        round_transpose_kernel<<<g2, 256>>>(W_out, p_woutT, DMODEL, DMODEL);
    }

    // 1) proj = qkv @ W_in + b_in   (output tf32-rounded)
    {
        dim3 grid(D3 / 128, TOKENS / 128);   // 24 x 64
        tf32_gemm_nt<<<grid, 256, NT_SMEM_BYTES>>>(qkv, p_winT, b_in, p_proj,
                                                   D3, DMODEL, 1);
    }

    // 2) attention -> ctx (128 Q rows / CTA, 256 threads, 2 CTAs/SM)
    {
        dim3 grid(SEQ / 128, BATCH * NHEADS);   // 16 x 64
        flash_attn_tc<<<grid, 256, FA_SMEM_BYTES>>>(p_proj, p_ctx);
    }

    // 3) out = ctx @ W_out + b_out  (fp32 output)
    {
        dim3 grid(DMODEL / 128, TOKENS / 128);  // 8 x 64
        tf32_gemm_nt<<<grid, 256, NT_SMEM_BYTES>>>(p_ctx, p_woutT, b_out, out,
                                                   DMODEL, DMODEL, 0);
    }
}

// round 14
// speedup vs baseline: 5.5689x; 1.0278x over previous
#include <cuda_runtime.h>
#include <cuda_bf16.h>
#include <cstdint>
#include <cstddef>

// Problem constants
#define BATCH 4
#define SEQ   2048
#define DMODEL 1024
#define NHEADS 16
#define HD     64
#define TOKENS (BATCH * SEQ)          // 8192
#define D3     (3 * DMODEL)           // 3072

// Scratch
__device__ float g_proj [(size_t)TOKENS * D3];      // 96 MB (tf32-rounded)
__device__ float g_ctx  [(size_t)TOKENS * DMODEL];  // 32 MB (tf32-rounded)
__device__ float g_winT [(size_t)D3 * DMODEL];      // 12 MB rounded W_in^T
__device__ float g_woutT[(size_t)DMODEL * DMODEL];  //  4 MB rounded W_out^T

__device__ __forceinline__ uint32_t f2tf32(float f) {
    uint32_t r;
    asm("cvt.rna.tf32.f32 %0, %1;" : "=r"(r) : "f"(f));
    return r;
}
__device__ __forceinline__ float roundtf(float f) { return __uint_as_float(f2tf32(f)); }

__device__ __forceinline__ void mma_tf32(
    float& c0, float& c1, float& c2, float& c3,
    uint32_t a0, uint32_t a1, uint32_t a2, uint32_t a3,
    uint32_t b0, uint32_t b1)
{
    asm volatile(
        "mma.sync.aligned.m16n8k8.row.col.f32.tf32.tf32.f32 "
        "{%0,%1,%2,%3}, {%4,%5,%6,%7}, {%8,%9}, {%0,%1,%2,%3};\n"
        : "+f"(c0), "+f"(c1), "+f"(c2), "+f"(c3)
        : "r"(a0), "r"(a1), "r"(a2), "r"(a3), "r"(b0), "r"(b1));
}

__device__ __forceinline__ void cp_async16(uint32_t dst, const void* src) {
    asm volatile("cp.async.cg.shared.global [%0], [%1], 16;" :: "r"(dst), "l"(src));
}
#define CP_COMMIT() asm volatile("cp.async.commit_group;")
#define CP_WAIT(n)  asm volatile("cp.async.wait_group %0;" :: "n"(n))

// ---------------------------------------------------------------------------
// Prepass: out[n][k] = round_tf32(in[k][n])
// ---------------------------------------------------------------------------
__global__ __launch_bounds__(256) void round_transpose_kernel(
    const float* __restrict__ in, float* __restrict__ out, int K, int N)
{
    __shared__ float t[32][33];
    const int k0 = blockIdx.y * 32;
    const int n0 = blockIdx.x * 32;
    const int tx = threadIdx.x & 31;
    const int ty = threadIdx.x >> 5;
    #pragma unroll
    for (int i = 0; i < 4; i++)
        t[ty + i * 8][tx] = in[(size_t)(k0 + ty + i * 8) * N + n0 + tx];
    __syncthreads();
    #pragma unroll
    for (int i = 0; i < 4; i++)
        out[(size_t)(n0 + ty + i * 8) * K + k0 + tx] = roundtf(t[tx][ty + i * 8]);
}

// ---------------------------------------------------------------------------
// TF32 NT GEMM (R13-proven, unchanged): C = A @ Bt^T + bias
// ---------------------------------------------------------------------------
#define OP_BYTES   16384
#define STG_BYTES  (2 * OP_BYTES)
#define NT_SMEM_BYTES (3 * STG_BYTES)          // 98304

__global__ __launch_bounds__(256, 2) void tf32_gemm_nt(
    const float* __restrict__ A, const float* __restrict__ Bt,
    const float* __restrict__ bias, float* __restrict__ C,
    int Ntot, int K, int round_out)
{
    extern __shared__ uint32_t smem[];
    const uint32_t smem_u32 = (uint32_t)__cvta_generic_to_shared(smem);

    const int tid  = threadIdx.x;
    const int lane = tid & 31;
    const int w    = tid >> 5;
    const int wm   = (w & 1) * 64;
    const int wn   = (w >> 1) * 32;
    const int m0   = blockIdx.y * 128;
    const int n0   = blockIdx.x * 128;

    const int r0 = tid >> 3;
    const int ch = tid & 7;

    const int krow_in = ((lane >> 4) << 3) + (lane & 7);
    const int kbit    = (lane >> 3) & 1;

    float acc[4][4][4];
    #pragma unroll
    for (int mt = 0; mt < 4; mt++)
        #pragma unroll
        for (int nt = 0; nt < 4; nt++)
            #pragma unroll
            for (int r = 0; r < 4; r++)
                acc[mt][nt][r] = 0.f;

    const int ITERS = K >> 5;

    auto stage = [&](int s, int k0) {
        const uint32_t aDst = smem_u32 + s * STG_BYTES;
        const uint32_t bDst = aDst + OP_BYTES;
        #pragma unroll
        for (int i = 0; i < 4; i++) {
            const int row = r0 + i * 32;
            const uint32_t off = row * 128 + ((ch ^ (row & 7)) << 4);
            cp_async16(aDst + off, A  + (size_t)(m0 + row) * K + k0 + ch * 4);
            cp_async16(bDst + off, Bt + (size_t)(n0 + row) * K + k0 + ch * 4);
        }
    };

    stage(0, 0);  CP_COMMIT();
    stage(1, 32); CP_COMMIT();

    for (int it = 0; it < ITERS; ++it) {
        if (it + 1 < ITERS) { CP_WAIT(1); } else { CP_WAIT(0); }
        __syncthreads();

        const uint32_t aBase = smem_u32 + (it % 3) * STG_BYTES;
        const uint32_t bBase = aBase + OP_BYTES;

        #pragma unroll
        for (int ks = 0; ks < 4; ks++) {
            uint32_t af[4][4];
            #pragma unroll
            for (int mt = 0; mt < 4; mt++) {
                const int row = wm + mt * 16 + (lane & 15);
                const int c = (ks << 1) + (lane >> 4);
                const uint32_t addr = aBase + row * 128 + ((c ^ (row & 7)) << 4);
                asm volatile(
                    "ldmatrix.sync.aligned.m8n8.x4.shared.b16 {%0,%1,%2,%3}, [%4];"
                    : "=r"(af[mt][0]), "=r"(af[mt][1]), "=r"(af[mt][2]), "=r"(af[mt][3])
                    : "r"(addr));
            }
            uint32_t bf[2][4];
            #pragma unroll
            for (int ntp = 0; ntp < 2; ntp++) {
                const int row = wn + ntp * 16 + krow_in;
                const int c = (ks << 1) + kbit;
                const uint32_t addr = bBase + row * 128 + ((c ^ (row & 7)) << 4);
                asm volatile(
                    "ldmatrix.sync.aligned.m8n8.x4.shared.b16 {%0,%1,%2,%3}, [%4];"
                    : "=r"(bf[ntp][0]), "=r"(bf[ntp][1]), "=r"(bf[ntp][2]), "=r"(bf[ntp][3])
                    : "r"(addr));
            }
            #pragma unroll
            for (int mt = 0; mt < 4; mt++)
                #pragma unroll
                for (int ntp = 0; ntp < 2; ntp++) {
                    mma_tf32(acc[mt][2*ntp][0], acc[mt][2*ntp][1],
                             acc[mt][2*ntp][2], acc[mt][2*ntp][3],
                             af[mt][0], af[mt][1], af[mt][2], af[mt][3],
                             bf[ntp][0], bf[ntp][1]);
                    mma_tf32(acc[mt][2*ntp+1][0], acc[mt][2*ntp+1][1],
                             acc[mt][2*ntp+1][2], acc[mt][2*ntp+1][3],
                             af[mt][0], af[mt][1], af[mt][2], af[mt][3],
                             bf[ntp][2], bf[ntp][3]);
                }
        }

        if (it + 2 < ITERS) {
            stage((it + 2) % 3, (it + 2) << 5);
            CP_COMMIT();
        }
    }

    #pragma unroll
    for (int mt = 0; mt < 4; mt++) {
        const int r0o = m0 + wm + mt * 16 + (lane >> 2);
        const int r1o = r0o + 8;
        #pragma unroll
        for (int nt = 0; nt < 4; nt++) {
            const int col = n0 + wn + nt * 8 + ((lane & 3) << 1);
            const float bx = bias[col], by = bias[col + 1];
            float2 v0 = { acc[mt][nt][0] + bx, acc[mt][nt][1] + by };
            float2 v1 = { acc[mt][nt][2] + bx, acc[mt][nt][3] + by };
            if (round_out) {
                v0.x = roundtf(v0.x); v0.y = roundtf(v0.y);
                v1.x = roundtf(v1.x); v1.y = roundtf(v1.y);
            }
            *(float2*)(C + (size_t)r0o * Ntot + col) = v0;
            *(float2*)(C + (size_t)r1o * Ntot + col) = v1;
        }
    }
}

// ---------------------------------------------------------------------------
// Flash attention, m-blocked: 128 threads = 4 warps, each warp owns 32 q-rows
// (two 16-row m-blocks). K fragments / V scalars loaded once per warp-tile,
// consumed by BOTH m-blocks -> ~0.63x L1 traffic per q-row vs R13.
// Smem identical to R13 (Ps aliased on Qs, 106,496 B) -> 2 CTAs/SM.
// ---------------------------------------------------------------------------
#define QS_OFF 0
#define PS_OFF 0
#define KT_OFF 8704
#define KT_BUF_WORDS (64 * 68)
#define VT_OFF (KT_OFF + 2 * KT_BUF_WORDS)
#define VT_BUF_WORDS (64 * 72)
#define FA_SMEM_WORDS (VT_OFF + 2 * VT_BUF_WORDS)
#define FA_SMEM_BYTES (FA_SMEM_WORDS * 4)            // 106496

__global__ __launch_bounds__(128) void flash_attn_tc(
    const float* __restrict__ proj, float* __restrict__ ctx)
{
    extern __shared__ uint32_t sm[];
    uint32_t* Qs = sm + QS_OFF;
    uint32_t* Ps = sm + PS_OFF;                      // aliased with Qs
    const uint32_t smem_u32 = (uint32_t)__cvta_generic_to_shared(sm);
    const uint32_t QsB = smem_u32 + QS_OFF * 4;
    const uint32_t PsB = smem_u32 + PS_OFF * 4;
    const uint32_t KtB = smem_u32 + KT_OFF * 4;
    const uint32_t VtB = smem_u32 + VT_OFF * 4;

    const int tid  = threadIdx.x;
    const int lane = tid & 31;
    const int w    = tid >> 5;          // 0..3
    const int wm   = w * 32;            // warp owns rows wm..wm+31
    const int b    = blockIdx.y >> 4;
    const int h    = blockIdx.y & 15;
    const int q0   = blockIdx.x * 128;

    const float* kptr = proj + (size_t)b * SEQ * D3 + DMODEL + h * HD;
    const float* vptr = kptr + DMODEL;

    // KV staging: 64 rows x 16 chunks x2 ops = 2048; 128 threads -> 8 rows each
    const int st_row = tid >> 4;          // 0..7
    const int st_c4  = (tid & 15) << 2;

    auto stage_kv = [&](int buf, int kv0) {
        const uint32_t kDst = KtB + buf * (KT_BUF_WORDS * 4);
        const uint32_t vDst = VtB + buf * (VT_BUF_WORDS * 4);
        #pragma unroll
        for (int i = 0; i < 8; i++) {
            const int row = st_row + i * 8;
            const size_t g = (size_t)(kv0 + row) * D3 + st_c4;
            cp_async16(kDst + (row * 68 + st_c4) * 4, kptr + g);
            cp_async16(vDst + (row * 72 + st_c4) * 4, vptr + g);
        }
    };

    // ---- stage Q (x0.125 exact on tf32 values) ----
    {
        const float* qptr = proj + (size_t)(b * SEQ + q0) * D3 + h * HD;
        #pragma unroll
        for (int i = 0; i < 16; i++) {
            const int f = tid + i * 128;
            const int row = f >> 4;
            const int c4 = (f & 15) << 2;
            float4 v = *(const float4*)(qptr + (size_t)row * D3 + c4);
            float4 t = { v.x * 0.125f, v.y * 0.125f, v.z * 0.125f, v.w * 0.125f };
            *(float4*)(Qs + row * 68 + c4) = t;
        }
    }

    stage_kv(0, 0);
    CP_COMMIT();
    __syncthreads();

    // ---- preload Q fragments for both m-blocks (Qs dead after; reused as Ps) ----
    uint32_t qf[2][8][4];
    #pragma unroll
    for (int mb = 0; mb < 2; mb++)
        #pragma unroll
        for (int ks = 0; ks < 8; ks++) {
            const uint32_t addr = QsB + (wm + mb * 16 + (lane & 15)) * 272
                                + ks * 32 + ((lane >> 4) << 4);
            asm volatile(
                "ldmatrix.sync.aligned.m8n8.x4.shared.b16 {%0,%1,%2,%3}, [%4];"
                : "=r"(qf[mb][ks][0]), "=r"(qf[mb][ks][1]),
                  "=r"(qf[mb][ks][2]), "=r"(qf[mb][ks][3])
                : "r"(addr));
        }

    float o[2][8][4];
    #pragma unroll
    for (int mb = 0; mb < 2; mb++)
        #pragma unroll
        for (int nt = 0; nt < 8; nt++)
            #pragma unroll
            for (int r = 0; r < 4; r++)
                o[mb][nt][r] = 0.f;
    float mv[2][2] = { {-1e30f, -1e30f}, {-1e30f, -1e30f} };
    float lv[2][2] = { {0.f, 0.f}, {0.f, 0.f} };

    int buf = 0;
    const int NTILES = SEQ / 64;

    const int krow_in = ((lane >> 4) << 3) + (lane & 7);
    const int kchunk  = ((lane >> 3) & 1) << 4;

    for (int t = 0; t < NTILES; ++t) {
        const bool has_next = (t + 1 < NTILES);
        if (has_next) {
            stage_kv(buf ^ 1, (t + 1) * 64);
            CP_COMMIT();
            CP_WAIT(1);
        } else {
            CP_WAIT(0);
        }
        __syncthreads();   // KV ready; orders Q preload reads before P stores (t=0)

        const uint32_t KtBuf = KtB + buf * (KT_BUF_WORDS * 4);
        const uint32_t* Vt = sm + VT_OFF + buf * VT_BUF_WORDS;

        // ---- S = Q K^T : K fragments shared by both m-blocks ----
        float s[2][8][4];
        #pragma unroll
        for (int mb = 0; mb < 2; mb++)
            #pragma unroll
            for (int nt = 0; nt < 8; nt++)
                #pragma unroll
                for (int r = 0; r < 4; r++)
                    s[mb][nt][r] = 0.f;

        #pragma unroll
        for (int ks = 0; ks < 8; ks++) {
            #pragma unroll
            for (int ntp = 0; ntp < 4; ntp++) {
                uint32_t kf[4];
                const uint32_t addr = KtBuf + (ntp * 16 + krow_in) * 272 + ks * 32 + kchunk;
                asm volatile(
                    "ldmatrix.sync.aligned.m8n8.x4.shared.b16 {%0,%1,%2,%3}, [%4];"
                    : "=r"(kf[0]), "=r"(kf[1]), "=r"(kf[2]), "=r"(kf[3])
                    : "r"(addr));
                #pragma unroll
                for (int mb = 0; mb < 2; mb++) {
                    mma_tf32(s[mb][2*ntp][0], s[mb][2*ntp][1],
                             s[mb][2*ntp][2], s[mb][2*ntp][3],
                             qf[mb][ks][0], qf[mb][ks][1], qf[mb][ks][2], qf[mb][ks][3],
                             kf[0], kf[1]);
                    mma_tf32(s[mb][2*ntp+1][0], s[mb][2*ntp+1][1],
                             s[mb][2*ntp+1][2], s[mb][2*ntp+1][3],
                             qf[mb][ks][0], qf[mb][ks][1], qf[mb][ks][2], qf[mb][ks][3],
                             kf[2], kf[3]);
                }
            }
        }

        // ---- online softmax + P store, per m-block ----
        #pragma unroll
        for (int mb = 0; mb < 2; mb++) {
            float mx0 = -1e30f, mx1 = -1e30f;
            #pragma unroll
            for (int nt = 0; nt < 8; nt++) {
                mx0 = fmaxf(mx0, fmaxf(s[mb][nt][0], s[mb][nt][1]));
                mx1 = fmaxf(mx1, fmaxf(s[mb][nt][2], s[mb][nt][3]));
            }
            mx0 = fmaxf(mx0, __shfl_xor_sync(0xffffffffu, mx0, 1));
            mx0 = fmaxf(mx0, __shfl_xor_sync(0xffffffffu, mx0, 2));
            mx1 = fmaxf(mx1, __shfl_xor_sync(0xffffffffu, mx1, 1));
            mx1 = fmaxf(mx1, __shfl_xor_sync(0xffffffffu, mx1, 2));

            const float mn0 = fmaxf(mv[mb][0], mx0);
            const float mn1 = fmaxf(mv[mb][1], mx1);
            const float a0 = __expf(mv[mb][0] - mn0);
            const float a1 = __expf(mv[mb][1] - mn1);
            mv[mb][0] = mn0; mv[mb][1] = mn1;

            float sum0 = 0.f, sum1 = 0.f;
            #pragma unroll
            for (int nt = 0; nt < 8; nt++) {
                s[mb][nt][0] = __expf(s[mb][nt][0] - mn0);
                s[mb][nt][1] = __expf(s[mb][nt][1] - mn0);
                s[mb][nt][2] = __expf(s[mb][nt][2] - mn1);
                s[mb][nt][3] = __expf(s[mb][nt][3] - mn1);
                sum0 += s[mb][nt][0] + s[mb][nt][1];
                sum1 += s[mb][nt][2] + s[mb][nt][3];
            }
            sum0 += __shfl_xor_sync(0xffffffffu, sum0, 1);
            sum0 += __shfl_xor_sync(0xffffffffu, sum0, 2);
            sum1 += __shfl_xor_sync(0xffffffffu, sum1, 1);
            sum1 += __shfl_xor_sync(0xffffffffu, sum1, 2);
            lv[mb][0] = lv[mb][0] * a0 + sum0;
            lv[mb][1] = lv[mb][1] * a1 + sum1;

            #pragma unroll
            for (int nt = 0; nt < 8; nt++) {
                o[mb][nt][0] *= a0; o[mb][nt][1] *= a0;
                o[mb][nt][2] *= a1; o[mb][nt][3] *= a1;
            }

            const int r = wm + mb * 16 + (lane >> 2);
            #pragma unroll
            for (int nt = 0; nt < 8; nt++) {
                uint32_t* p0 = Ps + r * 68 + nt * 8 + ((lane & 3) << 1);
                uint2 t0 = { f2tf32(s[mb][nt][0]), f2tf32(s[mb][nt][1]) };
                *(uint2*)p0 = t0;
                uint2 t1 = { f2tf32(s[mb][nt][2]), f2tf32(s[mb][nt][3]) };
                *(uint2*)(p0 + 8 * 68) = t1;
            }
        }
        __syncwarp();

        // ---- O += P V : V scalars shared by both m-blocks ----
        #pragma unroll
        for (int ks = 0; ks < 8; ks++) {
            uint32_t pf[2][4];
            #pragma unroll
            for (int mb = 0; mb < 2; mb++) {
                const uint32_t addr = PsB + (wm + mb * 16 + (lane & 15)) * 272
                                    + ks * 32 + ((lane >> 4) << 4);
                asm volatile(
                    "ldmatrix.sync.aligned.m8n8.x4.shared.b16 {%0,%1,%2,%3}, [%4];"
                    : "=r"(pf[mb][0]), "=r"(pf[mb][1]), "=r"(pf[mb][2]), "=r"(pf[mb][3])
                    : "r"(addr));
            }
            #pragma unroll
            for (int nt = 0; nt < 8; nt++) {
                const int base = (ks * 8 + (lane & 3)) * 72 + nt * 8 + (lane >> 2);
                const uint32_t b0 = Vt[base];
                const uint32_t b1 = Vt[base + 4 * 72];
                #pragma unroll
                for (int mb = 0; mb < 2; mb++)
                    mma_tf32(o[mb][nt][0], o[mb][nt][1], o[mb][nt][2], o[mb][nt][3],
                             pf[mb][0], pf[mb][1], pf[mb][2], pf[mb][3], b0, b1);
            }
        }

        __syncthreads();
        buf ^= 1;
    }

    // ---- epilogue ----
    #pragma unroll
    for (int mb = 0; mb < 2; mb++) {
        const float inv0 = 1.f / lv[mb][0];
        const float inv1 = 1.f / lv[mb][1];
        const int tok0 = b * SEQ + q0 + wm + mb * 16 + (lane >> 2);
        #pragma unroll
        for (int nt = 0; nt < 8; nt++) {
            const int col = h * HD + nt * 8 + ((lane & 3) << 1);
            float2 v0 = { roundtf(o[mb][nt][0] * inv0), roundtf(o[mb][nt][1] * inv0) };
            float2 v1 = { roundtf(o[mb][nt][2] * inv1), roundtf(o[mb][nt][3] * inv1) };
            *(float2*)(ctx + (size_t)tok0 * DMODEL + col) = v0;
            *(float2*)(ctx + (size_t)(tok0 + 8) * DMODEL + col) = v1;
        }
    }
}

// ---------------------------------------------------------------------------
// Launch
// ---------------------------------------------------------------------------
extern "C" void kernel_launch(void* const* d_in, const int* in_sizes, int n_in,
                              void* d_out, int out_size)
{
    const float* qkv   = (const float*)d_in[0];
    const float* W_in  = (const float*)d_in[1];
    const float* b_in  = (const float*)d_in[2];
    const float* W_out = (const float*)d_in[3];
    const float* b_out = (const float*)d_in[4];
    float* out = (float*)d_out;

    static float* p_proj = nullptr;
    static float* p_ctx  = nullptr;
    static float* p_winT = nullptr;
    static float* p_woutT = nullptr;
    if (!p_proj) {
        cudaGetSymbolAddress((void**)&p_proj, g_proj);
        cudaGetSymbolAddress((void**)&p_ctx,  g_ctx);
        cudaGetSymbolAddress((void**)&p_winT, g_winT);
        cudaGetSymbolAddress((void**)&p_woutT, g_woutT);
        cudaFuncSetAttribute(tf32_gemm_nt,
                             cudaFuncAttributeMaxDynamicSharedMemorySize, NT_SMEM_BYTES);
        cudaFuncSetAttribute(flash_attn_tc,
                             cudaFuncAttributeMaxDynamicSharedMemorySize, FA_SMEM_BYTES);
    }

    // 0) prepass: round+transpose weights (qkv fed raw; HMMA truncates A)
    {
        dim3 g1(D3 / 32, DMODEL / 32);
        round_transpose_kernel<<<g1, 256>>>(W_in, p_winT, DMODEL, D3);
        dim3 g2(DMODEL / 32, DMODEL / 32);
        round_transpose_kernel<<<g2, 256>>>(W_out, p_woutT, DMODEL, DMODEL);
    }

    // 1) proj = qkv @ W_in + b_in   (output tf32-rounded)
    {
        dim3 grid(D3 / 128, TOKENS / 128);
        tf32_gemm_nt<<<grid, 256, NT_SMEM_BYTES>>>(qkv, p_winT, b_in, p_proj,
                                                   D3, DMODEL, 1);
    }

    // 2) attention -> ctx (128 Q rows / CTA, 128 threads, 4 warps x 32 rows)
    {
        dim3 grid(SEQ / 128, BATCH * NHEADS);   // 16 x 64
        flash_attn_tc<<<grid, 128, FA_SMEM_BYTES>>>(p_proj, p_ctx);
    }

    // 3) out = ctx @ W_out + b_out  (fp32 output)
    {
        dim3 grid(DMODEL / 128, TOKENS / 128);
        tf32_gemm_nt<<<grid, 256, NT_SMEM_BYTES>>>(p_ctx, p_woutT, b_out, out,
                                                   DMODEL, DMODEL, 0);
    }
}

// round 15
// speedup vs baseline: 5.8774x; 1.0554x over previous
#include <cuda_runtime.h>
#include <cuda_bf16.h>
#include <cstdint>
#include <cstddef>

// Problem constants
#define BATCH 4
#define SEQ   2048
#define DMODEL 1024
#define NHEADS 16
#define HD     64
#define TOKENS (BATCH * SEQ)          // 8192
#define D3     (3 * DMODEL)           // 3072

// Scratch
__device__ float g_proj [(size_t)TOKENS * D3];      // 96 MB (tf32-rounded)
__device__ float g_ctx  [(size_t)TOKENS * DMODEL];  // 32 MB (tf32-rounded)
__device__ float g_winT [(size_t)D3 * DMODEL];      // 12 MB rounded W_in^T
__device__ float g_woutT[(size_t)DMODEL * DMODEL];  //  4 MB rounded W_out^T

__device__ __forceinline__ uint32_t f2tf32(float f) {
    uint32_t r;
    asm("cvt.rna.tf32.f32 %0, %1;" : "=r"(r) : "f"(f));
    return r;
}
__device__ __forceinline__ float roundtf(float f) { return __uint_as_float(f2tf32(f)); }

__device__ __forceinline__ void mma_tf32(
    float& c0, float& c1, float& c2, float& c3,
    uint32_t a0, uint32_t a1, uint32_t a2, uint32_t a3,
    uint32_t b0, uint32_t b1)
{
    asm volatile(
        "mma.sync.aligned.m16n8k8.row.col.f32.tf32.tf32.f32 "
        "{%0,%1,%2,%3}, {%4,%5,%6,%7}, {%8,%9}, {%0,%1,%2,%3};\n"
        : "+f"(c0), "+f"(c1), "+f"(c2), "+f"(c3)
        : "r"(a0), "r"(a1), "r"(a2), "r"(a3), "r"(b0), "r"(b1));
}

__device__ __forceinline__ void cp_async16(uint32_t dst, const void* src) {
    asm volatile("cp.async.cg.shared.global [%0], [%1], 16;" :: "r"(dst), "l"(src));
}
#define CP_COMMIT() asm volatile("cp.async.commit_group;")
#define CP_WAIT(n)  asm volatile("cp.async.wait_group %0;" :: "n"(n))

// ---------------------------------------------------------------------------
// Prepass: out[n][k] = round_tf32(in[k][n])
// ---------------------------------------------------------------------------
__global__ __launch_bounds__(256) void round_transpose_kernel(
    const float* __restrict__ in, float* __restrict__ out, int K, int N)
{
    __shared__ float t[32][33];
    const int k0 = blockIdx.y * 32;
    const int n0 = blockIdx.x * 32;
    const int tx = threadIdx.x & 31;
    const int ty = threadIdx.x >> 5;
    #pragma unroll
    for (int i = 0; i < 4; i++)
        t[ty + i * 8][tx] = in[(size_t)(k0 + ty + i * 8) * N + n0 + tx];
    __syncthreads();
    #pragma unroll
    for (int i = 0; i < 4; i++)
        out[(size_t)(n0 + ty + i * 8) * K + k0 + tx] = roundtf(t[tx][ty + i * 8]);
}

// ---------------------------------------------------------------------------
// TF32 NT GEMM: C = A @ Bt^T + bias. 128x128x32 CTA tile, 128 threads,
// 4 warps each owning 64x64. 3-stage cp.async ring, one barrier/iter.
// A may be raw fp32 (HMMA truncates); Bt pre-rounded.
// ---------------------------------------------------------------------------
#define OP_BYTES   16384
#define STG_BYTES  (2 * OP_BYTES)
#define NT_SMEM_BYTES (3 * STG_BYTES)          // 98304

__global__ __launch_bounds__(128, 2) void tf32_gemm_nt(
    const float* __restrict__ A, const float* __restrict__ Bt,
    const float* __restrict__ bias, float* __restrict__ C,
    int Ntot, int K, int round_out)
{
    extern __shared__ uint32_t smem[];
    const uint32_t smem_u32 = (uint32_t)__cvta_generic_to_shared(smem);

    const int tid  = threadIdx.x;
    const int lane = tid & 31;
    const int w    = tid >> 5;          // 0..3
    const int wm   = (w & 1) * 64;
    const int wn   = (w >> 1) * 64;
    const int m0   = blockIdx.y * 128;
    const int n0   = blockIdx.x * 128;

    // staging: 128 rows x 8 chunks per operand; 128 threads -> 8 rows each
    const int r0 = tid >> 3;       // 0..15
    const int ch = tid & 7;

    const int krow_in = ((lane >> 4) << 3) + (lane & 7);
    const int kbit    = (lane >> 3) & 1;

    float acc[4][8][4];
    #pragma unroll
    for (int mt = 0; mt < 4; mt++)
        #pragma unroll
        for (int nt = 0; nt < 8; nt++)
            #pragma unroll
            for (int r = 0; r < 4; r++)
                acc[mt][nt][r] = 0.f;

    const int ITERS = K >> 5;

    auto stage = [&](int s, int k0) {
        const uint32_t aDst = smem_u32 + s * STG_BYTES;
        const uint32_t bDst = aDst + OP_BYTES;
        #pragma unroll
        for (int i = 0; i < 8; i++) {
            const int row = r0 + i * 16;
            const uint32_t off = row * 128 + ((ch ^ (row & 7)) << 4);
            cp_async16(aDst + off, A  + (size_t)(m0 + row) * K + k0 + ch * 4);
            cp_async16(bDst + off, Bt + (size_t)(n0 + row) * K + k0 + ch * 4);
        }
    };

    stage(0, 0);  CP_COMMIT();
    stage(1, 32); CP_COMMIT();

    for (int it = 0; it < ITERS; ++it) {
        if (it + 1 < ITERS) { CP_WAIT(1); } else { CP_WAIT(0); }
        __syncthreads();

        const uint32_t aBase = smem_u32 + (it % 3) * STG_BYTES;
        const uint32_t bBase = aBase + OP_BYTES;

        #pragma unroll
        for (int ks = 0; ks < 4; ks++) {
            uint32_t af[4][4];
            #pragma unroll
            for (int mt = 0; mt < 4; mt++) {
                const int row = wm + mt * 16 + (lane & 15);
                const int c = (ks << 1) + (lane >> 4);
                const uint32_t addr = aBase + row * 128 + ((c ^ (row & 7)) << 4);
                asm volatile(
                    "ldmatrix.sync.aligned.m8n8.x4.shared.b16 {%0,%1,%2,%3}, [%4];"
                    : "=r"(af[mt][0]), "=r"(af[mt][1]), "=r"(af[mt][2]), "=r"(af[mt][3])
                    : "r"(addr));
            }
            uint32_t bf[4][4];
            #pragma unroll
            for (int ntp = 0; ntp < 4; ntp++) {
                const int row = wn + ntp * 16 + krow_in;
                const int c = (ks << 1) + kbit;
                const uint32_t addr = bBase + row * 128 + ((c ^ (row & 7)) << 4);
                asm volatile(
                    "ldmatrix.sync.aligned.m8n8.x4.shared.b16 {%0,%1,%2,%3}, [%4];"
                    : "=r"(bf[ntp][0]), "=r"(bf[ntp][1]), "=r"(bf[ntp][2]), "=r"(bf[ntp][3])
                    : "r"(addr));
            }
            #pragma unroll
            for (int mt = 0; mt < 4; mt++)
                #pragma unroll
                for (int ntp = 0; ntp < 4; ntp++) {
                    mma_tf32(acc[mt][2*ntp][0], acc[mt][2*ntp][1],
                             acc[mt][2*ntp][2], acc[mt][2*ntp][3],
                             af[mt][0], af[mt][1], af[mt][2], af[mt][3],
                             bf[ntp][0], bf[ntp][1]);
                    mma_tf32(acc[mt][2*ntp+1][0], acc[mt][2*ntp+1][1],
                             acc[mt][2*ntp+1][2], acc[mt][2*ntp+1][3],
                             af[mt][0], af[mt][1], af[mt][2], af[mt][3],
                             bf[ntp][2], bf[ntp][3]);
                }
        }

        if (it + 2 < ITERS) {
            stage((it + 2) % 3, (it + 2) << 5);
            CP_COMMIT();
        }
    }

    #pragma unroll
    for (int mt = 0; mt < 4; mt++) {
        const int r0o = m0 + wm + mt * 16 + (lane >> 2);
        const int r1o = r0o + 8;
        #pragma unroll
        for (int nt = 0; nt < 8; nt++) {
            const int col = n0 + wn + nt * 8 + ((lane & 3) << 1);
            const float bx = bias[col], by = bias[col + 1];
            float2 v0 = { acc[mt][nt][0] + bx, acc[mt][nt][1] + by };
            float2 v1 = { acc[mt][nt][2] + bx, acc[mt][nt][3] + by };
            if (round_out) {
                v0.x = roundtf(v0.x); v0.y = roundtf(v0.y);
                v1.x = roundtf(v1.x); v1.y = roundtf(v1.y);
            }
            *(float2*)(C + (size_t)r0o * Ntot + col) = v0;
            *(float2*)(C + (size_t)r1o * Ntot + col) = v1;
        }
    }
}

// ---------------------------------------------------------------------------
// Flash attention (R14 structure) + exp2 softmax + raw-fp32 P (HW truncation).
// 128 threads = 4 warps x 32 q-rows (two 16-row m-blocks); Ps aliased on Qs.
// Q prescaled by 0.125*log2(e); all exponentials via exp2f.
// ---------------------------------------------------------------------------
#define QS_OFF 0
#define PS_OFF 0
#define KT_OFF 8704
#define KT_BUF_WORDS (64 * 68)
#define VT_OFF (KT_OFF + 2 * KT_BUF_WORDS)
#define VT_BUF_WORDS (64 * 72)
#define FA_SMEM_WORDS (VT_OFF + 2 * VT_BUF_WORDS)
#define FA_SMEM_BYTES (FA_SMEM_WORDS * 4)            // 106496

#define QSCALE 0.1803368801111183f   // 0.125 * log2(e)

__global__ __launch_bounds__(128) void flash_attn_tc(
    const float* __restrict__ proj, float* __restrict__ ctx)
{
    extern __shared__ uint32_t sm[];
    uint32_t* Qs = sm + QS_OFF;
    float*    Ps = (float*)(sm + PS_OFF);            // aliased with Qs
    const uint32_t smem_u32 = (uint32_t)__cvta_generic_to_shared(sm);
    const uint32_t QsB = smem_u32 + QS_OFF * 4;
    const uint32_t PsB = smem_u32 + PS_OFF * 4;
    const uint32_t KtB = smem_u32 + KT_OFF * 4;
    const uint32_t VtB = smem_u32 + VT_OFF * 4;

    const int tid  = threadIdx.x;
    const int lane = tid & 31;
    const int w    = tid >> 5;
    const int wm   = w * 32;
    const int b    = blockIdx.y >> 4;
    const int h    = blockIdx.y & 15;
    const int q0   = blockIdx.x * 128;

    const float* kptr = proj + (size_t)b * SEQ * D3 + DMODEL + h * HD;
    const float* vptr = kptr + DMODEL;

    const int st_row = tid >> 4;
    const int st_c4  = (tid & 15) << 2;

    auto stage_kv = [&](int buf, int kv0) {
        const uint32_t kDst = KtB + buf * (KT_BUF_WORDS * 4);
        const uint32_t vDst = VtB + buf * (VT_BUF_WORDS * 4);
        #pragma unroll
        for (int i = 0; i < 8; i++) {
            const int row = st_row + i * 8;
            const size_t g = (size_t)(kv0 + row) * D3 + st_c4;
            cp_async16(kDst + (row * 68 + st_c4) * 4, kptr + g);
            cp_async16(vDst + (row * 72 + st_c4) * 4, vptr + g);
        }
    };

    // ---- stage Q scaled by 0.125*log2e ----
    {
        const float* qptr = proj + (size_t)(b * SEQ + q0) * D3 + h * HD;
        #pragma unroll
        for (int i = 0; i < 16; i++) {
            const int f = tid + i * 128;
            const int row = f >> 4;
            const int c4 = (f & 15) << 2;
            float4 v = *(const float4*)(qptr + (size_t)row * D3 + c4);
            float4 t = { v.x * QSCALE, v.y * QSCALE, v.z * QSCALE, v.w * QSCALE };
            *(float4*)(Qs + row * 68 + c4) = t;
        }
    }

    stage_kv(0, 0);
    CP_COMMIT();
    __syncthreads();

    // ---- preload Q fragments (Qs dead after; reused as Ps) ----
    uint32_t qf[2][8][4];
    #pragma unroll
    for (int mb = 0; mb < 2; mb++)
        #pragma unroll
        for (int ks = 0; ks < 8; ks++) {
            const uint32_t addr = QsB + (wm + mb * 16 + (lane & 15)) * 272
                                + ks * 32 + ((lane >> 4) << 4);
            asm volatile(
                "ldmatrix.sync.aligned.m8n8.x4.shared.b16 {%0,%1,%2,%3}, [%4];"
                : "=r"(qf[mb][ks][0]), "=r"(qf[mb][ks][1]),
                  "=r"(qf[mb][ks][2]), "=r"(qf[mb][ks][3])
                : "r"(addr));
        }

    float o[2][8][4];
    #pragma unroll
    for (int mb = 0; mb < 2; mb++)
        #pragma unroll
        for (int nt = 0; nt < 8; nt++)
            #pragma unroll
            for (int r = 0; r < 4; r++)
                o[mb][nt][r] = 0.f;
    float mv[2][2] = { {-1e30f, -1e30f}, {-1e30f, -1e30f} };
    float lv[2][2] = { {0.f, 0.f}, {0.f, 0.f} };

    int buf = 0;
    const int NTILES = SEQ / 64;

    const int krow_in = ((lane >> 4) << 3) + (lane & 7);
    const int kchunk  = ((lane >> 3) & 1) << 4;

    for (int t = 0; t < NTILES; ++t) {
        const bool has_next = (t + 1 < NTILES);
        if (has_next) {
            stage_kv(buf ^ 1, (t + 1) * 64);
            CP_COMMIT();
            CP_WAIT(1);
        } else {
            CP_WAIT(0);
        }
        __syncthreads();

        const uint32_t KtBuf = KtB + buf * (KT_BUF_WORDS * 4);
        const uint32_t* Vt = sm + VT_OFF + buf * VT_BUF_WORDS;

        // ---- S = Q K^T (log2-scaled scores) ----
        float s[2][8][4];
        #pragma unroll
        for (int mb = 0; mb < 2; mb++)
            #pragma unroll
            for (int nt = 0; nt < 8; nt++)
                #pragma unroll
                for (int r = 0; r < 4; r++)
                    s[mb][nt][r] = 0.f;

        #pragma unroll
        for (int ks = 0; ks < 8; ks++) {
            #pragma unroll
            for (int ntp = 0; ntp < 4; ntp++) {
                uint32_t kf[4];
                const uint32_t addr = KtBuf + (ntp * 16 + krow_in) * 272 + ks * 32 + kchunk;
                asm volatile(
                    "ldmatrix.sync.aligned.m8n8.x4.shared.b16 {%0,%1,%2,%3}, [%4];"
                    : "=r"(kf[0]), "=r"(kf[1]), "=r"(kf[2]), "=r"(kf[3])
                    : "r"(addr));
                #pragma unroll
                for (int mb = 0; mb < 2; mb++) {
                    mma_tf32(s[mb][2*ntp][0], s[mb][2*ntp][1],
                             s[mb][2*ntp][2], s[mb][2*ntp][3],
                             qf[mb][ks][0], qf[mb][ks][1], qf[mb][ks][2], qf[mb][ks][3],
                             kf[0], kf[1]);
                    mma_tf32(s[mb][2*ntp+1][0], s[mb][2*ntp+1][1],
                             s[mb][2*ntp+1][2], s[mb][2*ntp+1][3],
                             qf[mb][ks][0], qf[mb][ks][1], qf[mb][ks][2], qf[mb][ks][3],
                             kf[2], kf[3]);
                }
            }
        }

        // ---- online softmax (base-2) + P store ----
        #pragma unroll
        for (int mb = 0; mb < 2; mb++) {
            float mx0 = -1e30f, mx1 = -1e30f;
            #pragma unroll
            for (int nt = 0; nt < 8; nt++) {
                mx0 = fmaxf(mx0, fmaxf(s[mb][nt][0], s[mb][nt][1]));
                mx1 = fmaxf(mx1, fmaxf(s[mb][nt][2], s[mb][nt][3]));
            }
            mx0 = fmaxf(mx0, __shfl_xor_sync(0xffffffffu, mx0, 1));
            mx0 = fmaxf(mx0, __shfl_xor_sync(0xffffffffu, mx0, 2));
            mx1 = fmaxf(mx1, __shfl_xor_sync(0xffffffffu, mx1, 1));
            mx1 = fmaxf(mx1, __shfl_xor_sync(0xffffffffu, mx1, 2));

            const float mn0 = fmaxf(mv[mb][0], mx0);
            const float mn1 = fmaxf(mv[mb][1], mx1);
            const float a0 = exp2f(mv[mb][0] - mn0);
            const float a1 = exp2f(mv[mb][1] - mn1);
            mv[mb][0] = mn0; mv[mb][1] = mn1;

            float sum0 = 0.f, sum1 = 0.f;
            #pragma unroll
            for (int nt = 0; nt < 8; nt++) {
                s[mb][nt][0] = exp2f(s[mb][nt][0] - mn0);
                s[mb][nt][1] = exp2f(s[mb][nt][1] - mn0);
                s[mb][nt][2] = exp2f(s[mb][nt][2] - mn1);
                s[mb][nt][3] = exp2f(s[mb][nt][3] - mn1);
                sum0 += s[mb][nt][0] + s[mb][nt][1];
                sum1 += s[mb][nt][2] + s[mb][nt][3];
            }
            sum0 += __shfl_xor_sync(0xffffffffu, sum0, 1);
            sum0 += __shfl_xor_sync(0xffffffffu, sum0, 2);
            sum1 += __shfl_xor_sync(0xffffffffu, sum1, 1);
            sum1 += __shfl_xor_sync(0xffffffffu, sum1, 2);
            lv[mb][0] = lv[mb][0] * a0 + sum0;
            lv[mb][1] = lv[mb][1] * a1 + sum1;

            #pragma unroll
            for (int nt = 0; nt < 8; nt++) {
                o[mb][nt][0] *= a0; o[mb][nt][1] *= a0;
                o[mb][nt][2] *= a1; o[mb][nt][3] *= a1;
            }

            // P stored raw fp32 — HMMA truncates to tf32 at the PV MMA
            const int r = wm + mb * 16 + (lane >> 2);
            #pragma unroll
            for (int nt = 0; nt < 8; nt++) {
                float* p0 = Ps + r * 68 + nt * 8 + ((lane & 3) << 1);
                *(float2*)p0 = make_float2(s[mb][nt][0], s[mb][nt][1]);
                *(float2*)(p0 + 8 * 68) = make_float2(s[mb][nt][2], s[mb][nt][3]);
            }
        }
        __syncwarp();

        // ---- O += P V ----
        #pragma unroll
        for (int ks = 0; ks < 8; ks++) {
            uint32_t pf[2][4];
            #pragma unroll
            for (int mb = 0; mb < 2; mb++) {
                const uint32_t addr = PsB + (wm + mb * 16 + (lane & 15)) * 272
                                    + ks * 32 + ((lane >> 4) << 4);
                asm volatile(
                    "ldmatrix.sync.aligned.m8n8.x4.shared.b16 {%0,%1,%2,%3}, [%4];"
                    : "=r"(pf[mb][0]), "=r"(pf[mb][1]), "=r"(pf[mb][2]), "=r"(pf[mb][3])
                    : "r"(addr));
            }
            #pragma unroll
            for (int nt = 0; nt < 8; nt++) {
                const int base = (ks * 8 + (lane & 3)) * 72 + nt * 8 + (lane >> 2);
                const uint32_t b0 = Vt[base];
                const uint32_t b1 = Vt[base + 4 * 72];
                #pragma unroll
                for (int mb = 0; mb < 2; mb++)
                    mma_tf32(o[mb][nt][0], o[mb][nt][1], o[mb][nt][2], o[mb][nt][3],
                             pf[mb][0], pf[mb][1], pf[mb][2], pf[mb][3], b0, b1);
            }
        }

        __syncthreads();
        buf ^= 1;
    }

    // ---- epilogue ----
    #pragma unroll
    for (int mb = 0; mb < 2; mb++) {
        const float inv0 = 1.f / lv[mb][0];
        const float inv1 = 1.f / lv[mb][1];
        const int tok0 = b * SEQ + q0 + wm + mb * 16 + (lane >> 2);
        #pragma unroll
        for (int nt = 0; nt < 8; nt++) {
            const int col = h * HD + nt * 8 + ((lane & 3) << 1);
            float2 v0 = { roundtf(o[mb][nt][0] * inv0), roundtf(o[mb][nt][1] * inv0) };
            float2 v1 = { roundtf(o[mb][nt][2] * inv1), roundtf(o[mb][nt][3] * inv1) };
            *(float2*)(ctx + (size_t)tok0 * DMODEL + col) = v0;
            *(float2*)(ctx + (size_t)(tok0 + 8) * DMODEL + col) = v1;
        }
    }
}

// ---------------------------------------------------------------------------
// Launch
// ---------------------------------------------------------------------------
extern "C" void kernel_launch(void* const* d_in, const int* in_sizes, int n_in,
                              void* d_out, int out_size)
{
    const float* qkv   = (const float*)d_in[0];
    const float* W_in  = (const float*)d_in[1];
    const float* b_in  = (const float*)d_in[2];
    const float* W_out = (const float*)d_in[3];
    const float* b_out = (const float*)d_in[4];
    float* out = (float*)d_out;

    static float* p_proj = nullptr;
    static float* p_ctx  = nullptr;
    static float* p_winT = nullptr;
    static float* p_woutT = nullptr;
    if (!p_proj) {
        cudaGetSymbolAddress((void**)&p_proj, g_proj);
        cudaGetSymbolAddress((void**)&p_ctx,  g_ctx);
        cudaGetSymbolAddress((void**)&p_winT, g_winT);
        cudaGetSymbolAddress((void**)&p_woutT, g_woutT);
        cudaFuncSetAttribute(tf32_gemm_nt,
                             cudaFuncAttributeMaxDynamicSharedMemorySize, NT_SMEM_BYTES);
        cudaFuncSetAttribute(flash_attn_tc,
                             cudaFuncAttributeMaxDynamicSharedMemorySize, FA_SMEM_BYTES);
    }

    // 0) prepass: round+transpose weights
    {
        dim3 g1(D3 / 32, DMODEL / 32);
        round_transpose_kernel<<<g1, 256>>>(W_in, p_winT, DMODEL, D3);
        dim3 g2(DMODEL / 32, DMODEL / 32);
        round_transpose_kernel<<<g2, 256>>>(W_out, p_woutT, DMODEL, DMODEL);
    }

    // 1) proj = qkv @ W_in + b_in   (output tf32-rounded)
    {
        dim3 grid(D3 / 128, TOKENS / 128);
        tf32_gemm_nt<<<grid, 128, NT_SMEM_BYTES>>>(qkv, p_winT, b_in, p_proj,
                                                   D3, DMODEL, 1);
    }

    // 2) attention -> ctx
    {
        dim3 grid(SEQ / 128, BATCH * NHEADS);
        flash_attn_tc<<<grid, 128, FA_SMEM_BYTES>>>(p_proj, p_ctx);
    }

    // 3) out = ctx @ W_out + b_out
    {
        dim3 grid(DMODEL / 128, TOKENS / 128);
        tf32_gemm_nt<<<grid, 128, NT_SMEM_BYTES>>>(p_ctx, p_woutT, b_out, out,
                                                   DMODEL, DMODEL, 0);
    }
}

// round 17
// speedup vs baseline: 5.9380x; 1.0103x over previous
#include <cuda_runtime.h>
#include <cuda_bf16.h>
#include <cstdint>
#include <cstddef>

// Problem constants
#define BATCH 4
#define SEQ   2048
#define DMODEL 1024
#define NHEADS 16
#define HD     64
#define TOKENS (BATCH * SEQ)          // 8192
#define D3     (3 * DMODEL)           // 3072

// Scratch
__device__ float g_proj [(size_t)TOKENS * D3];      // 96 MB (tf32-rounded)
__device__ float g_ctx  [(size_t)TOKENS * DMODEL];  // 32 MB (tf32-rounded)
__device__ float g_winT [(size_t)D3 * DMODEL];      // 12 MB rounded W_in^T
__device__ float g_woutT[(size_t)DMODEL * DMODEL];  //  4 MB rounded W_out^T

__device__ __forceinline__ uint32_t f2tf32(float f) {
    uint32_t r;
    asm("cvt.rna.tf32.f32 %0, %1;" : "=r"(r) : "f"(f));
    return r;
}
__device__ __forceinline__ float roundtf(float f) { return __uint_as_float(f2tf32(f)); }

__device__ __forceinline__ void mma_tf32(
    float& c0, float& c1, float& c2, float& c3,
    uint32_t a0, uint32_t a1, uint32_t a2, uint32_t a3,
    uint32_t b0, uint32_t b1)
{
    asm volatile(
        "mma.sync.aligned.m16n8k8.row.col.f32.tf32.tf32.f32 "
        "{%0,%1,%2,%3}, {%4,%5,%6,%7}, {%8,%9}, {%0,%1,%2,%3};\n"
        : "+f"(c0), "+f"(c1), "+f"(c2), "+f"(c3)
        : "r"(a0), "r"(a1), "r"(a2), "r"(a3), "r"(b0), "r"(b1));
}

__device__ __forceinline__ void cp_async16(uint32_t dst, const void* src) {
    asm volatile("cp.async.cg.shared.global [%0], [%1], 16;" :: "r"(dst), "l"(src));
}
#define CP_COMMIT() asm volatile("cp.async.commit_group;")
#define CP_WAIT(n)  asm volatile("cp.async.wait_group %0;" :: "n"(n))

// ---------------------------------------------------------------------------
// Prepass: out[n][k] = round_tf32(in[k][n])
// ---------------------------------------------------------------------------
__global__ __launch_bounds__(256) void round_transpose_kernel(
    const float* __restrict__ in, float* __restrict__ out, int K, int N)
{
    __shared__ float t[32][33];
    const int k0 = blockIdx.y * 32;
    const int n0 = blockIdx.x * 32;
    const int tx = threadIdx.x & 31;
    const int ty = threadIdx.x >> 5;
    #pragma unroll
    for (int i = 0; i < 4; i++)
        t[ty + i * 8][tx] = in[(size_t)(k0 + ty + i * 8) * N + n0 + tx];
    __syncthreads();
    #pragma unroll
    for (int i = 0; i < 4; i++)
        out[(size_t)(n0 + ty + i * 8) * K + k0 + tx] = roundtf(t[tx][ty + i * 8]);
}

// ---------------------------------------------------------------------------
// TF32 NT GEMM, templated tile width: C[M, Ntot] = A @ Bt^T + bias.
// CTA tile 128 x NTILE x 32; 128 threads, 4 warps each 64 x (NTILE/2).
// 3-stage cp.async ring, one barrier per iter. A raw fp32 ok (HW truncates).
// ---------------------------------------------------------------------------
#define A_BYTES 16384
template <int NTILE>
__global__ __launch_bounds__(128, 2) void tf32_gemm_nt(
    const float* __restrict__ A, const float* __restrict__ Bt,
    const float* __restrict__ bias, float* __restrict__ C,
    int Ntot, int K, int round_out)
{
    constexpr int B_BYTES = NTILE * 128;
    constexpr int STG = A_BYTES + B_BYTES;
    constexpr int NT  = NTILE / 16;    // nt per warp (6 or 8)
    constexpr int NTPW = NTILE / 32;   // ldmatrix x4 per ks per warp (3 or 4)

    extern __shared__ uint32_t smem[];
    const uint32_t smem_u32 = (uint32_t)__cvta_generic_to_shared(smem);

    const int tid  = threadIdx.x;
    const int lane = tid & 31;
    const int w    = tid >> 5;
    const int wm   = (w & 1) * 64;
    const int wn   = (w >> 1) * (NTILE / 2);
    const int m0   = blockIdx.y * 128;
    const int n0   = blockIdx.x * NTILE;

    const int r0 = tid >> 3;       // 0..15
    const int ch = tid & 7;

    const int krow_in = ((lane >> 4) << 3) + (lane & 7);
    const int kbit    = (lane >> 3) & 1;

    float acc[4][NT][4];
    #pragma unroll
    for (int mt = 0; mt < 4; mt++)
        #pragma unroll
        for (int nt = 0; nt < NT; nt++)
            #pragma unroll
            for (int r = 0; r < 4; r++)
                acc[mt][nt][r] = 0.f;

    const int ITERS = K >> 5;

    auto stage = [&](int s, int k0) {
        const uint32_t aDst = smem_u32 + s * STG;
        const uint32_t bDst = aDst + A_BYTES;
        #pragma unroll
        for (int i = 0; i < 8; i++) {
            const int row = r0 + i * 16;
            const uint32_t off = row * 128 + ((ch ^ (row & 7)) << 4);
            cp_async16(aDst + off, A + (size_t)(m0 + row) * K + k0 + ch * 4);
        }
        #pragma unroll
        for (int i = 0; i < NTILE / 16; i++) {
            const int row = r0 + i * 16;
            const uint32_t off = row * 128 + ((ch ^ (row & 7)) << 4);
            cp_async16(bDst + off, Bt + (size_t)(n0 + row) * K + k0 + ch * 4);
        }
    };

    stage(0, 0);  CP_COMMIT();
    stage(1, 32); CP_COMMIT();

    for (int it = 0; it < ITERS; ++it) {
        if (it + 1 < ITERS) { CP_WAIT(1); } else { CP_WAIT(0); }
        __syncthreads();

        const uint32_t aBase = smem_u32 + (it % 3) * STG;
        const uint32_t bBase = aBase + A_BYTES;

        #pragma unroll
        for (int ks = 0; ks < 4; ks++) {
            uint32_t af[4][4];
            #pragma unroll
            for (int mt = 0; mt < 4; mt++) {
                const int row = wm + mt * 16 + (lane & 15);
                const int c = (ks << 1) + (lane >> 4);
                const uint32_t addr = aBase + row * 128 + ((c ^ (row & 7)) << 4);
                asm volatile(
                    "ldmatrix.sync.aligned.m8n8.x4.shared.b16 {%0,%1,%2,%3}, [%4];"
                    : "=r"(af[mt][0]), "=r"(af[mt][1]), "=r"(af[mt][2]), "=r"(af[mt][3])
                    : "r"(addr));
            }
            uint32_t bf[NTPW][4];
            #pragma unroll
            for (int ntp = 0; ntp < NTPW; ntp++) {
                const int row = wn + ntp * 16 + krow_in;
                const int c = (ks << 1) + kbit;
                const uint32_t addr = bBase + row * 128 + ((c ^ (row & 7)) << 4);
                asm volatile(
                    "ldmatrix.sync.aligned.m8n8.x4.shared.b16 {%0,%1,%2,%3}, [%4];"
                    : "=r"(bf[ntp][0]), "=r"(bf[ntp][1]), "=r"(bf[ntp][2]), "=r"(bf[ntp][3])
                    : "r"(addr));
            }
            #pragma unroll
            for (int mt = 0; mt < 4; mt++)
                #pragma unroll
                for (int ntp = 0; ntp < NTPW; ntp++) {
                    mma_tf32(acc[mt][2*ntp][0], acc[mt][2*ntp][1],
                             acc[mt][2*ntp][2], acc[mt][2*ntp][3],
                             af[mt][0], af[mt][1], af[mt][2], af[mt][3],
                             bf[ntp][0], bf[ntp][1]);
                    mma_tf32(acc[mt][2*ntp+1][0], acc[mt][2*ntp+1][1],
                             acc[mt][2*ntp+1][2], acc[mt][2*ntp+1][3],
                             af[mt][0], af[mt][1], af[mt][2], af[mt][3],
                             bf[ntp][2], bf[ntp][3]);
                }
        }

        if (it + 2 < ITERS) {
            stage((it + 2) % 3, (it + 2) << 5);
            CP_COMMIT();
        }
    }

    #pragma unroll
    for (int mt = 0; mt < 4; mt++) {
        const int r0o = m0 + wm + mt * 16 + (lane >> 2);
        const int r1o = r0o + 8;
        #pragma unroll
        for (int nt = 0; nt < NT; nt++) {
            const int col = n0 + wn + nt * 8 + ((lane & 3) << 1);
            const float bx = bias[col], by = bias[col + 1];
            float2 v0 = { acc[mt][nt][0] + bx, acc[mt][nt][1] + by };
            float2 v1 = { acc[mt][nt][2] + bx, acc[mt][nt][3] + by };
            if (round_out) {
                v0.x = roundtf(v0.x); v0.y = roundtf(v0.y);
                v1.x = roundtf(v1.x); v1.y = roundtf(v1.y);
            }
            *(float2*)(C + (size_t)r0o * Ntot + col) = v0;
            *(float2*)(C + (size_t)r1o * Ntot + col) = v1;
        }
    }
}

// ---------------------------------------------------------------------------
// Flash attention: R15 structure + l computed via tensor-core row-sum
// (extra MMA with constant B = 1.0 — removes sum shfls & FFMAs).
// 128 threads = 4 warps x 32 q-rows (two 16-row m-blocks); Ps aliased on Qs.
// ---------------------------------------------------------------------------
#define QS_OFF 0
#define PS_OFF 0
#define KT_OFF 8704
#define KT_BUF_WORDS (64 * 68)
#define VT_OFF (KT_OFF + 2 * KT_BUF_WORDS)
#define VT_BUF_WORDS (64 * 72)
#define FA_SMEM_WORDS (VT_OFF + 2 * VT_BUF_WORDS)
#define FA_SMEM_BYTES (FA_SMEM_WORDS * 4)            // 106496

#define QSCALE 0.1803368801111183f   // 0.125 * log2(e)
#define ONE_TF 0x3F800000u

__global__ __launch_bounds__(128) void flash_attn_tc(
    const float* __restrict__ proj, float* __restrict__ ctx)
{
    extern __shared__ uint32_t sm[];
    uint32_t* Qs = sm + QS_OFF;
    float*    Ps = (float*)(sm + PS_OFF);            // aliased with Qs
    const uint32_t smem_u32 = (uint32_t)__cvta_generic_to_shared(sm);
    const uint32_t QsB = smem_u32 + QS_OFF * 4;
    const uint32_t PsB = smem_u32 + PS_OFF * 4;
    const uint32_t KtB = smem_u32 + KT_OFF * 4;
    const uint32_t VtB = smem_u32 + VT_OFF * 4;

    const int tid  = threadIdx.x;
    const int lane = tid & 31;
    const int w    = tid >> 5;
    const int wm   = w * 32;
    const int b    = blockIdx.y >> 4;
    const int h    = blockIdx.y & 15;
    const int q0   = blockIdx.x * 128;

    const float* kptr = proj + (size_t)b * SEQ * D3 + DMODEL + h * HD;
    const float* vptr = kptr + DMODEL;

    const int st_row = tid >> 4;
    const int st_c4  = (tid & 15) << 2;

    auto stage_kv = [&](int buf, int kv0) {
        const uint32_t kDst = KtB + buf * (KT_BUF_WORDS * 4);
        const uint32_t vDst = VtB + buf * (VT_BUF_WORDS * 4);
        #pragma unroll
        for (int i = 0; i < 8; i++) {
            const int row = st_row + i * 8;
            const size_t g = (size_t)(kv0 + row) * D3 + st_c4;
            cp_async16(kDst + (row * 68 + st_c4) * 4, kptr + g);
            cp_async16(vDst + (row * 72 + st_c4) * 4, vptr + g);
        }
    };

    // ---- stage Q scaled by 0.125*log2e ----
    {
        const float* qptr = proj + (size_t)(b * SEQ + q0) * D3 + h * HD;
        #pragma unroll
        for (int i = 0; i < 16; i++) {
            const int f = tid + i * 128;
            const int row = f >> 4;
            const int c4 = (f & 15) << 2;
            float4 v = *(const float4*)(qptr + (size_t)row * D3 + c4);
            float4 t = { v.x * QSCALE, v.y * QSCALE, v.z * QSCALE, v.w * QSCALE };
            *(float4*)(Qs + row * 68 + c4) = t;
        }
    }

    stage_kv(0, 0);
    CP_COMMIT();
    __syncthreads();

    // ---- preload Q fragments (Qs dead after; reused as Ps) ----
    uint32_t qf[2][8][4];
    #pragma unroll
    for (int mb = 0; mb < 2; mb++)
        #pragma unroll
        for (int ks = 0; ks < 8; ks++) {
            const uint32_t addr = QsB + (wm + mb * 16 + (lane & 15)) * 272
                                + ks * 32 + ((lane >> 4) << 4);
            asm volatile(
                "ldmatrix.sync.aligned.m8n8.x4.shared.b16 {%0,%1,%2,%3}, [%4];"
                : "=r"(qf[mb][ks][0]), "=r"(qf[mb][ks][1]),
                  "=r"(qf[mb][ks][2]), "=r"(qf[mb][ks][3])
                : "r"(addr));
        }

    float o[2][8][4];
    #pragma unroll
    for (int mb = 0; mb < 2; mb++)
        #pragma unroll
        for (int nt = 0; nt < 8; nt++)
            #pragma unroll
            for (int r = 0; r < 4; r++)
                o[mb][nt][r] = 0.f;
    float lacc[2][4] = { {0.f, 0.f, 0.f, 0.f}, {0.f, 0.f, 0.f, 0.f} };
    float mv[2][2] = { {-1e30f, -1e30f}, {-1e30f, -1e30f} };

    int buf = 0;
    const int NTILES = SEQ / 64;

    const int krow_in = ((lane >> 4) << 3) + (lane & 7);
    const int kchunk  = ((lane >> 3) & 1) << 4;

    for (int t = 0; t < NTILES; ++t) {
        const bool has_next = (t + 1 < NTILES);
        if (has_next) {
            stage_kv(buf ^ 1, (t + 1) * 64);
            CP_COMMIT();
            CP_WAIT(1);
        } else {
            CP_WAIT(0);
        }
        __syncthreads();

        const uint32_t KtBuf = KtB + buf * (KT_BUF_WORDS * 4);
        const uint32_t* Vt = sm + VT_OFF + buf * VT_BUF_WORDS;

        // ---- S = Q K^T (log2-scaled) ----
        float s[2][8][4];
        #pragma unroll
        for (int mb = 0; mb < 2; mb++)
            #pragma unroll
            for (int nt = 0; nt < 8; nt++)
                #pragma unroll
                for (int r = 0; r < 4; r++)
                    s[mb][nt][r] = 0.f;

        #pragma unroll
        for (int ks = 0; ks < 8; ks++) {
            #pragma unroll
            for (int ntp = 0; ntp < 4; ntp++) {
                uint32_t kf[4];
                const uint32_t addr = KtBuf + (ntp * 16 + krow_in) * 272 + ks * 32 + kchunk;
                asm volatile(
                    "ldmatrix.sync.aligned.m8n8.x4.shared.b16 {%0,%1,%2,%3}, [%4];"
                    : "=r"(kf[0]), "=r"(kf[1]), "=r"(kf[2]), "=r"(kf[3])
                    : "r"(addr));
                #pragma unroll
                for (int mb = 0; mb < 2; mb++) {
                    mma_tf32(s[mb][2*ntp][0], s[mb][2*ntp][1],
                             s[mb][2*ntp][2], s[mb][2*ntp][3],
                             qf[mb][ks][0], qf[mb][ks][1], qf[mb][ks][2], qf[mb][ks][3],
                             kf[0], kf[1]);
                    mma_tf32(s[mb][2*ntp+1][0], s[mb][2*ntp+1][1],
                             s[mb][2*ntp+1][2], s[mb][2*ntp+1][3],
                             qf[mb][ks][0], qf[mb][ks][1], qf[mb][ks][2], qf[mb][ks][3],
                             kf[2], kf[3]);
                }
            }
        }

        // ---- online softmax (base-2): max + alpha rescale; l via MMA later ----
        #pragma unroll
        for (int mb = 0; mb < 2; mb++) {
            float mx0 = -1e30f, mx1 = -1e30f;
            #pragma unroll
            for (int nt = 0; nt < 8; nt++) {
                mx0 = fmaxf(mx0, fmaxf(s[mb][nt][0], s[mb][nt][1]));
                mx1 = fmaxf(mx1, fmaxf(s[mb][nt][2], s[mb][nt][3]));
            }
            mx0 = fmaxf(mx0, __shfl_xor_sync(0xffffffffu, mx0, 1));
            mx0 = fmaxf(mx0, __shfl_xor_sync(0xffffffffu, mx0, 2));
            mx1 = fmaxf(mx1, __shfl_xor_sync(0xffffffffu, mx1, 1));
            mx1 = fmaxf(mx1, __shfl_xor_sync(0xffffffffu, mx1, 2));

            const float mn0 = fmaxf(mv[mb][0], mx0);
            const float mn1 = fmaxf(mv[mb][1], mx1);
            const float a0 = exp2f(mv[mb][0] - mn0);
            const float a1 = exp2f(mv[mb][1] - mn1);
            mv[mb][0] = mn0; mv[mb][1] = mn1;

            #pragma unroll
            for (int nt = 0; nt < 8; nt++) {
                s[mb][nt][0] = exp2f(s[mb][nt][0] - mn0);
                s[mb][nt][1] = exp2f(s[mb][nt][1] - mn0);
                s[mb][nt][2] = exp2f(s[mb][nt][2] - mn1);
                s[mb][nt][3] = exp2f(s[mb][nt][3] - mn1);
            }

            #pragma unroll
            for (int nt = 0; nt < 8; nt++) {
                o[mb][nt][0] *= a0; o[mb][nt][1] *= a0;
                o[mb][nt][2] *= a1; o[mb][nt][3] *= a1;
            }
            lacc[mb][0] *= a0; lacc[mb][1] *= a0;
            lacc[mb][2] *= a1; lacc[mb][3] *= a1;

            // P stored raw fp32 — HMMA truncates to tf32
            const int r = wm + mb * 16 + (lane >> 2);
            #pragma unroll
            for (int nt = 0; nt < 8; nt++) {
                float* p0 = Ps + r * 68 + nt * 8 + ((lane & 3) << 1);
                *(float2*)p0 = make_float2(s[mb][nt][0], s[mb][nt][1]);
                *(float2*)(p0 + 8 * 68) = make_float2(s[mb][nt][2], s[mb][nt][3]);
            }
        }
        __syncwarp();

        // ---- O += P V, plus l += P @ ones (constant B) ----
        #pragma unroll
        for (int ks = 0; ks < 8; ks++) {
            uint32_t pf[2][4];
            #pragma unroll
            for (int mb = 0; mb < 2; mb++) {
                const uint32_t addr = PsB + (wm + mb * 16 + (lane & 15)) * 272
                                    + ks * 32 + ((lane >> 4) << 4);
                asm volatile(
                    "ldmatrix.sync.aligned.m8n8.x4.shared.b16 {%0,%1,%2,%3}, [%4];"
                    : "=r"(pf[mb][0]), "=r"(pf[mb][1]), "=r"(pf[mb][2]), "=r"(pf[mb][3])
                    : "r"(addr));
            }
            #pragma unroll
            for (int nt = 0; nt < 8; nt++) {
                const int base = (ks * 8 + (lane & 3)) * 72 + nt * 8 + (lane >> 2);
                const uint32_t b0 = Vt[base];
                const uint32_t b1 = Vt[base + 4 * 72];
                #pragma unroll
                for (int mb = 0; mb < 2; mb++)
                    mma_tf32(o[mb][nt][0], o[mb][nt][1], o[mb][nt][2], o[mb][nt][3],
                             pf[mb][0], pf[mb][1], pf[mb][2], pf[mb][3], b0, b1);
            }
            #pragma unroll
            for (int mb = 0; mb < 2; mb++)
                mma_tf32(lacc[mb][0], lacc[mb][1], lacc[mb][2], lacc[mb][3],
                         pf[mb][0], pf[mb][1], pf[mb][2], pf[mb][3],
                         ONE_TF, ONE_TF);
        }

        __syncthreads();
        buf ^= 1;
    }

    // ---- epilogue ----
    #pragma unroll
    for (int mb = 0; mb < 2; mb++) {
        const float inv0 = 1.f / lacc[mb][0];
        const float inv1 = 1.f / lacc[mb][2];
        const int tok0 = b * SEQ + q0 + wm + mb * 16 + (lane >> 2);
        #pragma unroll
        for (int nt = 0; nt < 8; nt++) {
            const int col = h * HD + nt * 8 + ((lane & 3) << 1);
            float2 v0 = { roundtf(o[mb][nt][0] * inv0), roundtf(o[mb][nt][1] * inv0) };
            float2 v1 = { roundtf(o[mb][nt][2] * inv1), roundtf(o[mb][nt][3] * inv1) };
            *(float2*)(ctx + (size_t)tok0 * DMODEL + col) = v0;
            *(float2*)(ctx + (size_t)(tok0 + 8) * DMODEL + col) = v1;
        }
    }
}

// ---------------------------------------------------------------------------
// Launch
// ---------------------------------------------------------------------------
extern "C" void kernel_launch(void* const* d_in, const int* in_sizes, int n_in,
                              void* d_out, int out_size)
{
    const float* qkv   = (const float*)d_in[0];
    const float* W_in  = (const float*)d_in[1];
    const float* b_in  = (const float*)d_in[2];
    const float* W_out = (const float*)d_in[3];
    const float* b_out = (const float*)d_in[4];
    float* out = (float*)d_out;

    static float* p_proj = nullptr;
    static float* p_ctx  = nullptr;
    static float* p_winT = nullptr;
    static float* p_woutT = nullptr;
    if (!p_proj) {
        cudaGetSymbolAddress((void**)&p_proj, g_proj);
        cudaGetSymbolAddress((void**)&p_ctx,  g_ctx);
        cudaGetSymbolAddress((void**)&p_winT, g_winT);
        cudaGetSymbolAddress((void**)&p_woutT, g_woutT);
        cudaFuncSetAttribute(tf32_gemm_nt<96>,
                             cudaFuncAttributeMaxDynamicSharedMemorySize,
                             3 * (A_BYTES + 96 * 128));
        cudaFuncSetAttribute(tf32_gemm_nt<128>,
                             cudaFuncAttributeMaxDynamicSharedMemorySize,
                             3 * (A_BYTES + 128 * 128));
        cudaFuncSetAttribute(flash_attn_tc,
                             cudaFuncAttributeMaxDynamicSharedMemorySize, FA_SMEM_BYTES);
    }

    // 0) prepass: round+transpose weights (qkv fed raw; HMMA truncates A)
    {
        dim3 g1(D3 / 32, DMODEL / 32);
        round_transpose_kernel<<<g1, 256>>>(W_in, p_winT, DMODEL, D3);
        dim3 g2(DMODEL / 32, DMODEL / 32);
        round_transpose_kernel<<<g2, 256>>>(W_out, p_woutT, DMODEL, DMODEL);
    }

    // 1) proj = qkv @ W_in + b_in   (96-wide tiles -> 2048 CTAs, ~fine waves)
    {
        dim3 grid(D3 / 96, TOKENS / 128);   // 32 x 64
        tf32_gemm_nt<96><<<grid, 128, 3 * (A_BYTES + 96 * 128)>>>(
            qkv, p_winT, b_in, p_proj, D3, DMODEL, 1);
    }

    // 2) attention -> ctx
    {
        dim3 grid(SEQ / 128, BATCH * NHEADS);
        flash_attn_tc<<<grid, 128, FA_SMEM_BYTES>>>(p_proj, p_ctx);
    }

    // 3) out = ctx @ W_out + b_out
    {
        dim3 grid(DMODEL / 128, TOKENS / 128);
        tf32_gemm_nt<128><<<grid, 128, 3 * (A_BYTES + 128 * 128)>>>(
            p_ctx, p_woutT, b_out, out, DMODEL, DMODEL, 0);
    }
}